// round 12
// baseline (speedup 1.0000x reference)
#include <cuda_runtime.h>
#include <cuda_fp16.h>
#include <cstdint>

#define HEADS 8
#define DH 32
#define LMK 128
#define FDIM 256
#define NP 4096LL

#define OFF_XN   0LL
#define OFF_Q    (OFF_XN + NP*FDIM)
#define OFF_K    (OFF_Q  + HEADS*NP*DH)
#define OFF_V    (OFF_K  + HEADS*NP*DH)
#define OFF_KT   (OFF_V  + HEADS*NP*DH)
#define OFF_QL   (OFF_KT + HEADS*NP*DH)
#define OFF_KLT  (OFF_QL + HEADS*LMK*DH)
#define OFF_A1   (OFF_KLT+ HEADS*DH*LMK)
#define OFF_A2   (OFF_A1 + HEADS*NP*LMK)
#define OFF_A3   (OFF_A2 + HEADS*LMK*LMK)
#define OFF_Z    (OFF_A3 + HEADS*LMK*NP)
#define OFF_Z2   (OFF_Z  + HEADS*LMK*LMK)
#define OFF_AZ   (OFF_Z2 + HEADS*LMK*LMK)
#define OFF_T1   (OFF_AZ + HEADS*LMK*LMK)
#define OFF_T2   (OFF_T1 + HEADS*LMK*LMK)
#define OFF_AV   (OFF_T2 + HEADS*LMK*LMK)
#define OFF_OCAT (OFF_AV + HEADS*LMK*DH)
#define OFF_PROJ (OFF_OCAT+ NP*FDIM)
#define OFF_AVP  (OFF_PROJ+ NP*FDIM)
#define OFF_H16  (OFF_AVP + 16LL*HEADS*LMK*DH)

#define HB  (HEADS*LMK*NP)
#define H_A12F 0LL
#define H_A3   (H_A12F + HB)
#define H_A1T  (H_A3   + HB)
#define H_XNT  (H_A1T  + 2*HB)
#define H_WQ   (H_XNT  + 2*NP*FDIM)
#define H_ZI   (H_WQ   + 2*FDIM*768LL)
#define H_OCT  (H_ZI   + 2*HEADS*LMK*LMK)
#define H_WO   (H_OCT  + 2*NP*FDIM)
#define H_END  (H_WO   + 2*FDIM*FDIM)
#define TOTALF (OFF_H16 + (H_END + 1)/2)

__device__ __align__(128) float g_buf[TOTALF];
__device__ int g_rowmax;

// ---------- LayerNorm + front pad (also zeroes g_rowmax) ----------
__global__ void __launch_bounds__(256) ln_kernel(const float* __restrict__ x,
                                                 const float* __restrict__ g,
                                                 const float* __restrict__ b,
                                                 int pad)
{
    if (blockIdx.x == 0 && threadIdx.x == 0) g_rowmax = 0;
    int r = blockIdx.x, c = threadIdx.x;
    float* xn = g_buf + OFF_XN;
    if (r < pad) { xn[(long long)r*FDIM + c] = 0.f; return; }
    float v = x[(long long)(r - pad)*FDIM + c];
    float s = v, s2 = v*v;
    #pragma unroll
    for (int o = 16; o; o >>= 1) {
        s  += __shfl_xor_sync(0xffffffffu, s,  o);
        s2 += __shfl_xor_sync(0xffffffffu, s2, o);
    }
    __shared__ float ss[8], ss2[8];
    int w = c >> 5;
    if ((c & 31) == 0) { ss[w] = s; ss2[w] = s2; }
    __syncthreads();
    s = 0.f; s2 = 0.f;
    #pragma unroll
    for (int i = 0; i < 8; i++) { s += ss[i]; s2 += ss2[i]; }
    float mean = s * (1.f/256.f);
    float var  = s2 * (1.f/256.f) - mean*mean;
    xn[(long long)r*FDIM + c] = (v - mean) * rsqrtf(var + 1e-5f) * g[c] + b[c];
}

// ---------- fp32 tile GEMM (small K=32 score GEMMs) ----------
__global__ void __launch_bounds__(256, 2) bgemm128(
    float* __restrict__ C, const float* __restrict__ A, const float* __restrict__ B,
    int Ni, int Ki, long long sA, long long sB, long long sC)
{
    A += (long long)blockIdx.z * sA;
    B += (long long)blockIdx.z * sB;
    C += (long long)blockIdx.z * sC;
    const int m0 = blockIdx.y * 128, n0 = blockIdx.x * 128;
    __shared__ float As[8][128];
    __shared__ float Bs[8][128];
    const int tid = threadIdx.x;
    const int tx = tid & 15, ty = tid >> 4;
    float acc[8][8];
    #pragma unroll
    for (int i = 0; i < 8; i++)
        #pragma unroll
        for (int j = 0; j < 8; j++) acc[i][j] = 0.f;
    const int am = tid >> 1, ak = (tid & 1) << 2;
    const int bk = tid >> 5, bn = (tid & 31) << 2;
    for (int k0 = 0; k0 < Ki; k0 += 8) {
        float4 a4 = *(const float4*)(A + (long long)(m0 + am)*Ki + (k0 + ak));
        float4 b4 = *(const float4*)(B + (long long)(k0 + bk)*Ni + (n0 + bn));
        As[ak+0][am] = a4.x; As[ak+1][am] = a4.y; As[ak+2][am] = a4.z; As[ak+3][am] = a4.w;
        *(float4*)&Bs[bk][bn] = b4;
        __syncthreads();
        #pragma unroll
        for (int kk = 0; kk < 8; kk++) {
            float a[8], b[8];
            *(float4*)(a)     = *(const float4*)&As[kk][ty*4];
            *(float4*)(a + 4) = *(const float4*)&As[kk][64 + ty*4];
            *(float4*)(b)     = *(const float4*)&Bs[kk][tx*4];
            *(float4*)(b + 4) = *(const float4*)&Bs[kk][64 + tx*4];
            #pragma unroll
            for (int i = 0; i < 8; i++)
                #pragma unroll
                for (int j = 0; j < 8; j++)
                    acc[i][j] += a[i]*b[j];
        }
        __syncthreads();
    }
    #pragma unroll
    for (int i = 0; i < 8; i++) {
        int m = m0 + ((i >> 2) << 6) + ty*4 + (i & 3);
        #pragma unroll
        for (int jh = 0; jh < 2; jh++) {
            float4 r;
            r.x = acc[i][jh*4+0]; r.y = acc[i][jh*4+1];
            r.z = acc[i][jh*4+2]; r.w = acc[i][jh*4+3];
            *(float4*)(C + (long long)m*Ni + n0 + jh*64 + tx*4) = r;
        }
    }
}

// ---------- fused Newton-Schulz pinv (4-CTA cluster per head) ----------
__device__ __forceinline__ void csync() {
    asm volatile("barrier.cluster.arrive.aligned;" ::: "memory");
    asm volatile("barrier.cluster.wait.aligned;" ::: "memory");
}

__device__ __forceinline__ void gemm64_dev(
    float* __restrict__ C, const float* __restrict__ A, const float* __restrict__ B,
    int m0, int n0, float ids, float es, float alpha,
    float (*As)[64], float (*Bs)[64])
{
    int tid = threadIdx.x;
    int tx = tid & 15, ty = tid >> 4;
    float acc[4][4];
    #pragma unroll
    for (int i = 0; i < 4; i++)
        #pragma unroll
        for (int j = 0; j < 4; j++) acc[i][j] = 0.f;
    int am = tid >> 2, ak = (tid & 3) << 2;
    int bk = tid >> 4, bn = (tid & 15) << 2;
    for (int k0 = 0; k0 < 128; k0 += 16) {
        float4 a4 = *(const float4*)(A + (m0 + am)*128 + k0 + ak);
        float4 b4 = *(const float4*)(B + (k0 + bk)*128 + n0 + bn);
        b4.x *= es; b4.y *= es; b4.z *= es; b4.w *= es;
        int kg = k0 + bk, ng = n0 + bn;
        if      (kg == ng)     b4.x += ids;
        else if (kg == ng + 1) b4.y += ids;
        else if (kg == ng + 2) b4.z += ids;
        else if (kg == ng + 3) b4.w += ids;
        As[ak+0][am] = a4.x; As[ak+1][am] = a4.y; As[ak+2][am] = a4.z; As[ak+3][am] = a4.w;
        *(float4*)&Bs[bk][bn] = b4;
        __syncthreads();
        #pragma unroll
        for (int kk = 0; kk < 16; kk++) {
            float a[4], b[4];
            *(float4*)a = *(const float4*)&As[kk][ty*4];
            *(float4*)b = *(const float4*)&Bs[kk][tx*4];
            #pragma unroll
            for (int i = 0; i < 4; i++)
                #pragma unroll
                for (int j = 0; j < 4; j++) acc[i][j] += a[i]*b[j];
        }
        __syncthreads();
    }
    #pragma unroll
    for (int i = 0; i < 4; i++) {
        float4 r;
        r.x = alpha*acc[i][0]; r.y = alpha*acc[i][1];
        r.z = alpha*acc[i][2]; r.w = alpha*acc[i][3];
        *(float4*)(C + (m0 + ty*4 + i)*128 + n0 + tx*4) = r;
    }
}

__global__ void __cluster_dims__(4,1,1) __launch_bounds__(256) pinv_fused()
{
    __shared__ float As[16][64];
    __shared__ float Bs[16][64];
    int q = blockIdx.x, h = blockIdx.y;
    int m0 = (q >> 1) * 64, n0 = (q & 1) * 64;
    long long s2 = (long long)LMK*LMK;
    float* A2 = g_buf + OFF_A2 + h*s2;
    float* Z  = g_buf + OFF_Z  + h*s2;
    float* Z2 = g_buf + OFF_Z2 + h*s2;
    float* AZ = g_buf + OFF_AZ + h*s2;
    float* T1 = g_buf + OFF_T1 + h*s2;
    float* T2 = g_buf + OFF_T2 + h*s2;
    float* zi = Z; float* zo = Z2;
    #pragma unroll 1
    for (int it = 0; it < 6; it++) {
        gemm64_dev(AZ, A2, zi, m0, n0, 0.f,   1.f, 1.f,   As, Bs); csync();
        gemm64_dev(T1, AZ, AZ, m0, n0, 7.f,  -1.f, 1.f,   As, Bs); csync();
        gemm64_dev(T2, AZ, T1, m0, n0, 15.f, -1.f, 1.f,   As, Bs); csync();
        gemm64_dev(zo, zi, T2, m0, n0, 13.f, -1.f, 0.25f, As, Bs); csync();
        float* t = zi; zi = zo; zo = t;
    }
}

// ---------- landmark means (8 warps / block) ----------
__global__ void __launch_bounds__(256) landmarks(int N)
{
    int h = blockIdx.y;
    int w = threadIdx.x >> 5, lane = threadIdx.x & 31;
    int i = blockIdx.x * 8 + w;
    int l = N / LMK;
    const float* q = g_buf + OFF_Q + ((long long)h*N + (long long)i*l)*DH;
    const float* k = g_buf + OFF_K + ((long long)h*N + (long long)i*l)*DH;
    float sq = 0.f, sk = 0.f;
    for (int r = 0; r < l; r++) { sq += q[r*DH + lane]; sk += k[r*DH + lane]; }
    float inv = 1.f / (float)l;
    g_buf[OFF_QL  + ((long long)h*LMK + i)*DH + lane] = sq * inv;
    g_buf[OFF_KLT + ((long long)h*DH + lane)*LMK + i] = sk * inv;
}

// ---------- generic row softmax (L<=256) ----------
template <int CNT>
__global__ void softmax_rows(float* __restrict__ p, int L)
{
    long long row = blockIdx.x;
    float* r = p + row * (long long)L;
    float v[CNT];
    float mx = -1e30f;
    #pragma unroll
    for (int t = 0; t < CNT; t++) {
        int i = threadIdx.x + t*256;
        v[t] = (i < L) ? r[i] : -1e30f;
        mx = fmaxf(mx, v[t]);
    }
    #pragma unroll
    for (int o = 16; o; o >>= 1) mx = fmaxf(mx, __shfl_xor_sync(0xffffffffu, mx, o));
    __shared__ float sh[8], sh2[8];
    int w = threadIdx.x >> 5;
    if ((threadIdx.x & 31) == 0) sh[w] = mx;
    __syncthreads();
    mx = sh[0];
    #pragma unroll
    for (int i = 1; i < 8; i++) mx = fmaxf(mx, sh[i]);
    float sum = 0.f;
    #pragma unroll
    for (int t = 0; t < CNT; t++) {
        int i = threadIdx.x + t*256;
        if (i < L) { v[t] = __expf(v[t] - mx); sum += v[t]; }
    }
    #pragma unroll
    for (int o = 16; o; o >>= 1) sum += __shfl_xor_sync(0xffffffffu, sum, o);
    if ((threadIdx.x & 31) == 0) sh2[w] = sum;
    __syncthreads();
    sum = 0.f;
    #pragma unroll
    for (int i = 0; i < 8; i++) sum += sh2[i];
    float inv = 1.f / sum;
    #pragma unroll
    for (int t = 0; t < CNT; t++) {
        int i = threadIdx.x + t*256;
        if (i < L) r[i] = v[t] * inv;
    }
}

// ---------- fused softmax(A1) + transpose + fp16 hi/lo split ----------
__global__ void __launch_bounds__(256) softmax_a1_split(
        const float* __restrict__ A1, __half* __restrict__ hi,
        __half* __restrict__ lo, int N)
{
    __shared__ float sm[32][132];
    int h = blockIdx.y, t0 = blockIdx.x * 32;
    const float* base = A1 + ((long long)h*N + t0)*LMK;
    for (int i = threadIdx.x; i < 32*32; i += 256) {
        int r = i >> 5, c4 = (i & 31) << 2;
        *(float4*)&sm[r][c4] = *(const float4*)(base + r*LMK + c4);
    }
    __syncthreads();
    int w = threadIdx.x >> 5, lane = threadIdx.x & 31;
    #pragma unroll
    for (int j = 0; j < 4; j++) {
        int r = w*4 + j;
        float v0 = sm[r][lane], v1 = sm[r][lane+32], v2 = sm[r][lane+64], v3 = sm[r][lane+96];
        float mx = fmaxf(fmaxf(v0, v1), fmaxf(v2, v3));
        #pragma unroll
        for (int o = 16; o; o >>= 1) mx = fmaxf(mx, __shfl_xor_sync(0xffffffffu, mx, o));
        v0 = __expf(v0 - mx); v1 = __expf(v1 - mx); v2 = __expf(v2 - mx); v3 = __expf(v3 - mx);
        float s = v0 + v1 + v2 + v3;
        #pragma unroll
        for (int o = 16; o; o >>= 1) s += __shfl_xor_sync(0xffffffffu, s, o);
        float inv = 1.f / s;
        sm[r][lane] = v0*inv; sm[r][lane+32] = v1*inv;
        sm[r][lane+64] = v2*inv; sm[r][lane+96] = v3*inv;
    }
    __syncthreads();
    #pragma unroll
    for (int j = 0; j < 16; j++) {
        int k = w*16 + j;
        float v = sm[lane][k];
        __half hv = __float2half(v);
        __half lv = __float2half(v - __half2float(hv));
        long long o = ((long long)h*LMK + k)*N + t0 + lane;
        hi[o] = hv; lo[o] = lv;
    }
}

// ---------- A3 softmax (L = N), emits fp16 ONLY ----------
__global__ void __launch_bounds__(256) softmax_a3(const float* __restrict__ p,
                                                  __half* __restrict__ ph, int L)
{
    long long row = blockIdx.x;
    const float* r = p + row * (long long)L;
    __half* rh = ph + row * (long long)L;
    float v[16];
    float mx = -1e30f;
    #pragma unroll
    for (int t = 0; t < 16; t++) {
        int i = threadIdx.x + t*256;
        v[t] = r[i];
        mx = fmaxf(mx, v[t]);
    }
    #pragma unroll
    for (int o = 16; o; o >>= 1) mx = fmaxf(mx, __shfl_xor_sync(0xffffffffu, mx, o));
    __shared__ float sh[8], sh2[8];
    int w = threadIdx.x >> 5;
    if ((threadIdx.x & 31) == 0) sh[w] = mx;
    __syncthreads();
    mx = sh[0];
    #pragma unroll
    for (int i = 1; i < 8; i++) mx = fmaxf(mx, sh[i]);
    float sum = 0.f;
    #pragma unroll
    for (int t = 0; t < 16; t++) { v[t] = __expf(v[t] - mx); sum += v[t]; }
    #pragma unroll
    for (int o = 16; o; o >>= 1) sum += __shfl_xor_sync(0xffffffffu, sum, o);
    if ((threadIdx.x & 31) == 0) sh2[w] = sum;
    __syncthreads();
    sum = 0.f;
    #pragma unroll
    for (int i = 0; i < 8; i++) sum += sh2[i];
    float inv = 1.f / sum;
    #pragma unroll
    for (int t = 0; t < 16; t++) {
        int i = threadIdx.x + t*256;
        rh[i] = __float2half(v[t] * inv);
    }
}

// ---------- pinv norm ----------
__global__ void colmax_a2()
{
    int h = blockIdx.x, j = threadIdx.x;
    const float* a = g_buf + OFF_A2 + (long long)h*LMK*LMK;
    float s = 0.f;
    for (int i = 0; i < LMK; i++) s += a[i*LMK + j];
    #pragma unroll
    for (int o = 16; o; o >>= 1) s = fmaxf(s, __shfl_xor_sync(0xffffffffu, s, o));
    __shared__ float sh[4];
    if ((j & 31) == 0) sh[j >> 5] = s;
    __syncthreads();
    if (j == 0) {
        s = fmaxf(fmaxf(sh[0], sh[1]), fmaxf(sh[2], sh[3]));
        atomicMax(&g_rowmax, __float_as_int(s));
    }
}

__global__ void zinit()
{
    long long idx = (long long)blockIdx.x * 256 + threadIdx.x;
    if (idx >= (long long)HEADS*LMK*LMK) return;
    int h = (int)(idx >> 14), rem = (int)(idx & 16383);
    int i = rem >> 7, j = rem & 127;
    float row = __int_as_float(g_rowmax);
    g_buf[OFF_Z + idx] = g_buf[OFF_A2 + ((long long)h*LMK + j)*LMK + i] / row;
}

// ---------- av = attn3(fp16) @ v, split-K ----------
#define AVKC 16
__global__ void __launch_bounds__(256) av_part(const __half* __restrict__ A3h, int N)
{
    int kc = blockIdx.x, h = blockIdx.y;
    const int KLEN = N / AVKC;
    __shared__ float vs[256*32];
    const float* vh = g_buf + OFF_V + ((long long)h*N + (long long)kc*KLEN)*DH;
    for (int i = threadIdx.x; i < KLEN*DH/4; i += 256)
        ((float4*)vs)[i] = ((const float4*)vh)[i];
    __syncthreads();
    int warp = threadIdx.x >> 5, lane = threadIdx.x & 31;
    for (int r = warp; r < LMK; r += 8) {
        const __half* arow = A3h + ((long long)h*LMK + r)*N + kc*KLEN;
        float acc = 0.f;
        #pragma unroll 2
        for (int k = 0; k < KLEN; k += 8) {
            __half2 a01 = *(const __half2*)(arow + k);
            __half2 a23 = *(const __half2*)(arow + k + 2);
            __half2 a45 = *(const __half2*)(arow + k + 4);
            __half2 a67 = *(const __half2*)(arow + k + 6);
            float2 f01 = __half22float2(a01), f23 = __half22float2(a23);
            float2 f45 = __half22float2(a45), f67 = __half22float2(a67);
            acc += f01.x * vs[(k+0)*DH + lane] + f01.y * vs[(k+1)*DH + lane];
            acc += f23.x * vs[(k+2)*DH + lane] + f23.y * vs[(k+3)*DH + lane];
            acc += f45.x * vs[(k+4)*DH + lane] + f45.y * vs[(k+5)*DH + lane];
            acc += f67.x * vs[(k+6)*DH + lane] + f67.y * vs[(k+7)*DH + lane];
        }
        g_buf[OFF_AVP + ((long long)kc*HEADS*LMK + (long long)h*LMK + r)*DH + lane] = acc;
    }
}
__global__ void av_reduce()
{
    int idx = blockIdx.x*256 + threadIdx.x;
    if (idx >= HEADS*LMK*DH) return;
    float s = 0.f;
    #pragma unroll
    for (int kc = 0; kc < AVKC; kc++)
        s += g_buf[OFF_AVP + (long long)kc*HEADS*LMK*DH + idx];
    g_buf[OFF_AV + idx] = s;
}

// ---------- ocat = concat_h( a12(fp16) @ av + depthwise_conv(v) ) ----------
__global__ void __launch_bounds__(128) ocat_kernel(const float* __restrict__ rk,
                                                   const __half* __restrict__ A12f, int N)
{
    int h = blockIdx.y, tid = threadIdx.x;
    int t = blockIdx.x * 128 + tid;
    __shared__ float avs[LMK][32];
    __shared__ float kr[33];
    const float* av = g_buf + OFF_AV + (long long)h*LMK*DH;
    #pragma unroll
    for (int c4 = 0; c4 < 8; c4++)
        *(float4*)&avs[tid][c4*4] = *(const float4*)(av + tid*DH + c4*4);
    if (tid < 33) kr[tid] = rk[h*33 + tid];
    __syncthreads();
    const __half* a12row = A12f + ((long long)h*N + t)*LMK;
    float acc[32];
    #pragma unroll
    for (int c = 0; c < 32; c++) acc[c] = 0.f;
    for (int k = 0; k < LMK; k += 2) {
        __half2 a2 = *(const __half2*)(a12row + k);
        float2 af = __half22float2(a2);
        #pragma unroll
        for (int c = 0; c < 32; c++) acc[c] += af.x * avs[k][c] + af.y * avs[k+1][c];
    }
    const float* vh = g_buf + OFF_V + (long long)h*N*DH;
    for (int j = 0; j < 33; j++) {
        int tt = t + j - 16;
        if (tt >= 0 && tt < N) {
            float w = kr[j];
            const float4* vr = (const float4*)(vh + (long long)tt*DH);
            #pragma unroll
            for (int c4 = 0; c4 < 8; c4++) {
                float4 vv = vr[c4];
                acc[c4*4+0] += w*vv.x; acc[c4*4+1] += w*vv.y;
                acc[c4*4+2] += w*vv.z; acc[c4*4+3] += w*vv.w;
            }
        }
    }
    float* o = g_buf + OFF_OCAT + (long long)t*FDIM + h*DH;
    #pragma unroll
    for (int c4 = 0; c4 < 8; c4++)
        *(float4*)(o + c4*4) = make_float4(acc[c4*4], acc[c4*4+1], acc[c4*4+2], acc[c4*4+3]);
}

// ---------- final residual epilogue ----------
__global__ void epilogue(const float* __restrict__ x, const float* __restrict__ b_out,
                         float* __restrict__ out, int pad)
{
    int t = blockIdx.x, c = threadIdx.x;
    long long i = (long long)t*FDIM + c;
    out[i] = x[i] + g_buf[OFF_PROJ + (long long)(t + pad)*FDIM + c] + b_out[c];
}

__global__ void tail_k(float* p, float a, float b) { p[0] = a; p[1] = b; }

// ============= fp16 prep kernels =============
__global__ void __launch_bounds__(256) split_h(const float* __restrict__ src,
                                               __half* __restrict__ hi,
                                               __half* __restrict__ lo,
                                               long long total4)
{
    long long i = (long long)blockIdx.x*256 + threadIdx.x;
    if (i >= total4) return;
    float4 v = ((const float4*)src)[i];
    __half h0 = __float2half(v.x), h1 = __float2half(v.y);
    __half h2 = __float2half(v.z), h3 = __float2half(v.w);
    __half l0 = __float2half(v.x - __half2float(h0));
    __half l1 = __float2half(v.y - __half2float(h1));
    __half l2 = __float2half(v.z - __half2float(h2));
    __half l3 = __float2half(v.w - __half2float(h3));
    ((ushort4*)hi)[i] = make_ushort4(__half_as_ushort(h0), __half_as_ushort(h1),
                                     __half_as_ushort(h2), __half_as_ushort(h3));
    ((ushort4*)lo)[i] = make_ushort4(__half_as_ushort(l0), __half_as_ushort(l1),
                                     __half_as_ushort(l2), __half_as_ushort(l3));
}

__global__ void __launch_bounds__(256) splitT_h(const float* __restrict__ src,
                                                __half* __restrict__ hi,
                                                __half* __restrict__ lo,
                                                int M, int K)
{
    __shared__ float t[32][33];
    long long bs = (long long)blockIdx.z * M * K;
    int m0 = blockIdx.x * 32, k0 = blockIdx.y * 32;
    int tx = threadIdx.x & 31, ty = threadIdx.x >> 5;
    #pragma unroll
    for (int j = 0; j < 4; j++) {
        int ml = ty + 8*j;
        t[ml][tx] = src[bs + (long long)(m0 + ml)*K + k0 + tx];
    }
    __syncthreads();
    #pragma unroll
    for (int j = 0; j < 4; j++) {
        int kl = ty + 8*j;
        float v = t[tx][kl];
        __half hv = __float2half(v);
        __half lv = __float2half(v - __half2float(hv));
        long long o = bs + (long long)(k0 + kl)*M + m0 + tx;
        hi[o] = hv; lo[o] = lv;
    }
}

// ============= mma helpers =============
__device__ __forceinline__ void ldsm4(uint32_t* r, uint32_t addr) {
    asm volatile("ldmatrix.sync.aligned.m8n8.x4.shared.b16 {%0,%1,%2,%3}, [%4];"
        : "=r"(r[0]), "=r"(r[1]), "=r"(r[2]), "=r"(r[3]) : "r"(addr));
}
__device__ __forceinline__ void ldsm4t(uint32_t* r, uint32_t addr) {
    asm volatile("ldmatrix.sync.aligned.m8n8.x4.trans.shared.b16 {%0,%1,%2,%3}, [%4];"
        : "=r"(r[0]), "=r"(r[1]), "=r"(r[2]), "=r"(r[3]) : "r"(addr));
}
__device__ __forceinline__ void mma16816(float* c, const uint32_t* a, const uint32_t* b) {
    asm volatile("mma.sync.aligned.m16n8k16.row.col.f32.f16.f16.f32 "
        "{%0,%1,%2,%3}, {%4,%5,%6,%7}, {%8,%9}, {%0,%1,%2,%3};"
        : "+f"(c[0]), "+f"(c[1]), "+f"(c[2]), "+f"(c[3])
        : "r"(a[0]), "r"(a[1]), "r"(a[2]), "r"(a[3]), "r"(b[0]), "r"(b[1]));
}
__device__ __forceinline__ void cpasync16(uint32_t saddr, const void* gaddr) {
    asm volatile("cp.async.cg.shared.global [%0], [%1], 16;\n" :: "r"(saddr), "l"(gaddr));
}
__device__ __forceinline__ void cpcommit() { asm volatile("cp.async.commit_group;\n"); }
template <int NN>
__device__ __forceinline__ void cpwait() { asm volatile("cp.async.wait_group %0;\n" :: "n"(NN)); }
__device__ __forceinline__ void stcs2(float* p, float x, float y) {
    asm volatile("st.global.cs.v2.f32 [%0], {%1,%2};" :: "l"(p), "f"(x), "f"(y) : "memory");
}

// ============= pipelined fp16 3-prod GEMM, templated epilogue =============
// EPI 0: write fp32 C (+ optional fp16 Ch)
// EPI 1: qkv scatter: write Q(scaled)/K/KT/V directly (ldA = token count)
// EPI 2: write ONLY fp16 Ch
template <int EPI>
__global__ void __launch_bounds__(256, 2) hgemm3(float* __restrict__ C,
        const __half* __restrict__ Ah, const __half* __restrict__ Al,
        const __half* __restrict__ Bh, const __half* __restrict__ Bl,
        int ldA, int N, int K, long long sA, long long sB, long long sC,
        __half* __restrict__ Ch)
{
    constexpr int D = 3;
    Ah += (long long)blockIdx.z * sA;  Al += (long long)blockIdx.z * sA;
    Bh += (long long)blockIdx.z * sB;  Bl += (long long)blockIdx.z * sB;
    if (EPI == 0) C  += (long long)blockIdx.z * sC;
    if (Ch) Ch += (long long)blockIdx.z * sC;
    const int m0 = blockIdx.y * 128, n0 = blockIdx.x * 128;

    extern __shared__ __align__(16) uint8_t dsm[];
    const uint32_t sb = (uint32_t)__cvta_generic_to_shared(dsm);
    const int tid = threadIdx.x, lane = tid & 31, warp = tid >> 5;
    const int wm = warp >> 1, wn = warp & 1;

    const int T = K >> 5;
    int li0 = tid, li1 = tid + 256;
    int lk0 = li0 >> 4, ls0 = li0 & 15;
    int lk1 = li1 >> 4, ls1 = li1 & 15;
    uint32_t d0 = (uint32_t)(lk0*256 + ((ls0 ^ (lk0 & 7)) << 4));
    uint32_t d1 = (uint32_t)(lk1*256 + ((ls1 ^ (lk1 & 7)) << 4));

    auto load_stage = [&](int stage, int chunk) {
        int kb = chunk << 5;
        uint32_t s0 = sb + (uint32_t)(stage*4) * 8192u;
        long long ga0 = (long long)(kb + lk0)*ldA + m0 + ls0*8;
        long long ga1 = (long long)(kb + lk1)*ldA + m0 + ls1*8;
        long long gb0 = (long long)(kb + lk0)*N   + n0 + ls0*8;
        long long gb1 = (long long)(kb + lk1)*N   + n0 + ls1*8;
        cpasync16(s0 +         d0, Ah + ga0);  cpasync16(s0 +         d1, Ah + ga1);
        cpasync16(s0 +  8192 + d0, Al + ga0);  cpasync16(s0 +  8192 + d1, Al + ga1);
        cpasync16(s0 + 16384 + d0, Bh + gb0);  cpasync16(s0 + 16384 + d1, Bh + gb1);
        cpasync16(s0 + 24576 + d0, Bl + gb0);  cpasync16(s0 + 24576 + d1, Bl + gb1);
    };

    float acc[2][8][4];
    #pragma unroll
    for (int i = 0; i < 2; i++)
        #pragma unroll
        for (int j = 0; j < 8; j++)
            #pragma unroll
            for (int q = 0; q < 4; q++) acc[i][j][q] = 0.f;

    #pragma unroll
    for (int s = 0; s < D-1; s++) {
        if (s < T) load_stage(s, s);
        cpcommit();
    }

    for (int it = 0; it < T; it++) {
        cpwait<D-2>();
        __syncthreads();
        int st = it % D;
        uint32_t sA0 = sb + (uint32_t)(st*4) * 8192u;

        #pragma unroll
        for (int ks = 0; ks < 32; ks += 16) {
            uint32_t ah[2][4], al[2][4];
            #pragma unroll
            for (int mt = 0; mt < 2; mt++) {
                int kr  = ks + (lane & 7) + ((lane >> 4) << 3);
                int seg = (wm*4 + mt*2) + ((lane >> 3) & 1);
                uint32_t a = (uint32_t)(kr*256 + ((seg ^ (kr & 7)) << 4));
                ldsm4t(ah[mt], sA0 + a);
                ldsm4t(al[mt], sA0 + 8192 + a);
            }
            #pragma unroll
            for (int np = 0; np < 4; np++) {
                int kr  = ks + (lane & 7) + (((lane >> 3) & 1) << 3);
                int seg = (wn*8 + np*2) + ((lane >> 4) & 1);
                uint32_t a = (uint32_t)(kr*256 + ((seg ^ (kr & 7)) << 4));
                uint32_t bh[4], bl[4];
                ldsm4t(bh, sA0 + 16384 + a);
                ldsm4t(bl, sA0 + 24576 + a);
                #pragma unroll
                for (int mt = 0; mt < 2; mt++) {
                    mma16816(acc[mt][np*2+0], ah[mt], bh + 0);
                    mma16816(acc[mt][np*2+0], al[mt], bh + 0);
                    mma16816(acc[mt][np*2+0], ah[mt], bl + 0);
                    mma16816(acc[mt][np*2+1], ah[mt], bh + 2);
                    mma16816(acc[mt][np*2+1], al[mt], bh + 2);
                    mma16816(acc[mt][np*2+1], ah[mt], bl + 2);
                }
            }
        }
        int nx = it + D - 1;
        if (nx < T) load_stage(nx % D, nx);
        cpcommit();
    }

    const int g = lane >> 2, t4 = lane & 3;
    #pragma unroll
    for (int mt = 0; mt < 2; mt++) {
        int mb = m0 + wm*32 + mt*16 + g;
        #pragma unroll
        for (int nt = 0; nt < 8; nt++) {
            int n = n0 + wn*64 + nt*8 + t4*2;
            #pragma unroll
            for (int half = 0; half < 2; half++) {
                int m = mb + half*8;
                float vx = acc[mt][nt][half*2+0], vy = acc[mt][nt][half*2+1];
                if (EPI == 1) {
                    int which = n >> 8, inner = n & 255;
                    int hh = inner >> 5, dd = inner & 31;
                    long long o = ((long long)hh*ldA + m)*DH + dd;
                    if (which == 0) {
                        g_buf[OFF_Q + o]   = vx * 0.17677669529663688f;
                        g_buf[OFF_Q + o+1] = vy * 0.17677669529663688f;
                    } else if (which == 1) {
                        g_buf[OFF_K + o]   = vx;
                        g_buf[OFF_K + o+1] = vy;
                        g_buf[OFF_KT + ((long long)hh*DH + dd)*ldA + m]     = vx;
                        g_buf[OFF_KT + ((long long)hh*DH + dd + 1)*ldA + m] = vy;
                    } else {
                        g_buf[OFF_V + o]   = vx;
                        g_buf[OFF_V + o+1] = vy;
                    }
                } else {
                    if (EPI == 0)
                        *(float2*)(C + (long long)m*N + n) = make_float2(vx, vy);
                    if (Ch)
                        *(__half2*)(Ch + (long long)m*N + n) = __floats2half2_rn(vx, vy);
                }
            }
        }
    }
}

// ============= att = a12 @ attn3 : A row-major, 2-chunk pipeline =============
__global__ void __launch_bounds__(256, 2) attmma(float* __restrict__ out, int N,
        const __half* __restrict__ A, const __half* __restrict__ B)
{
    const int h = blockIdx.z;
    A += (long long)h * N * LMK;
    B += (long long)h * LMK * N;
    out += (long long)h * N * N;
    const int m0 = blockIdx.y * 128, n0 = blockIdx.x * 128;

    extern __shared__ __align__(16) uint8_t dsm[];
    const uint32_t sb = (uint32_t)__cvta_generic_to_shared(dsm);
    const int tid = threadIdx.x, lane = tid & 31, warp = tid >> 5;
    const int wm = warp >> 1, wn = warp & 1;

    #pragma unroll
    for (int rep = 0; rep < 4; rep++) {
        int i = tid + rep*256;
        int r = i >> 3, s = i & 7;
        uint32_t dA = (uint32_t)(r*256 + ((s ^ (r & 7)) << 4));
        cpasync16(sb + dA, A + (long long)(m0 + r)*LMK + s*8);
    }
    #pragma unroll
    for (int rep = 0; rep < 4; rep++) {
        int i = tid + rep*256;
        int k = i >> 4, s = i & 15;
        uint32_t dB = (uint32_t)(k*256 + ((s ^ (k & 7)) << 4));
        cpasync16(sb + 32768 + dB, B + (long long)k*N + n0 + s*8);
    }
    cpcommit();
    #pragma unroll
    for (int rep = 0; rep < 4; rep++) {
        int i = tid + rep*256;
        int r = i >> 3, s = 8 + (i & 7);
        uint32_t dA = (uint32_t)(r*256 + ((s ^ (r & 7)) << 4));
        cpasync16(sb + dA, A + (long long)(m0 + r)*LMK + s*8);
    }
    #pragma unroll
    for (int rep = 0; rep < 4; rep++) {
        int i = tid + rep*256;
        int k = 64 + (i >> 4), s = i & 15;
        uint32_t dB = (uint32_t)(k*256 + ((s ^ (k & 7)) << 4));
        cpasync16(sb + 32768 + dB, B + (long long)k*N + n0 + s*8);
    }
    cpcommit();

    float acc[2][8][4];
    #pragma unroll
    for (int i = 0; i < 2; i++)
        #pragma unroll
        for (int j = 0; j < 8; j++)
            #pragma unroll
            for (int q = 0; q < 4; q++) acc[i][j][q] = 0.f;

    cpwait<1>();
    __syncthreads();

    #pragma unroll 1
    for (int half = 0; half < 2; half++) {
        if (half == 1) { cpwait<0>(); __syncthreads(); }
        #pragma unroll
        for (int ks = half*64; ks < half*64 + 64; ks += 16) {
            uint32_t ah[2][4];
            #pragma unroll
            for (int mt = 0; mt < 2; mt++) {
                int r   = wm*32 + mt*16 + (lane & 7) + ((lane >> 3) & 1)*8;
                int seg = (ks >> 3) + ((lane >> 4) & 1);
                uint32_t a = (uint32_t)(r*256 + ((seg ^ (r & 7)) << 4));
                ldsm4(ah[mt], sb + a);
            }
            #pragma unroll
            for (int np = 0; np < 4; np++) {
                int kr  = ks + (lane & 7) + (((lane >> 3) & 1) << 3);
                int seg = (wn*8 + np*2) + ((lane >> 4) & 1);
                uint32_t a = (uint32_t)(kr*256 + ((seg ^ (kr & 7)) << 4));
                uint32_t bh[4];
                ldsm4t(bh, sb + 32768 + a);
                #pragma unroll
                for (int mt = 0; mt < 2; mt++) {
                    mma16816(acc[mt][np*2+0], ah[mt], bh + 0);
                    mma16816(acc[mt][np*2+1], ah[mt], bh + 2);
                }
            }
        }
    }

    const int g = lane >> 2, t4 = lane & 3;
    #pragma unroll
    for (int mt = 0; mt < 2; mt++) {
        int m = m0 + wm*32 + mt*16 + g;
        #pragma unroll
        for (int nt = 0; nt < 8; nt++) {
            int n = n0 + wn*64 + nt*8 + t4*2;
            stcs2(out + (long long)m*N + n,     acc[mt][nt][0], acc[mt][nt][1]);
            stcs2(out + (long long)(m+8)*N + n, acc[mt][nt][2], acc[mt][nt][3]);
        }
    }
}

// =======================================================================
extern "C" void kernel_launch(void* const* d_in, const int* in_sizes, int n_in,
                              void* d_out, int out_size)
{
    const float* x     = (const float*)d_in[0];
    const float* ln_g  = (const float*)d_in[1];
    const float* ln_b  = (const float*)d_in[2];
    const float* w_qkv = (const float*)d_in[3];
    const float* w_out = (const float*)d_in[4];
    const float* b_out = (const float*)d_in[5];
    const float* rk    = (const float*)d_in[6];
    float* out = (float*)d_out;

    int n   = in_sizes[0] / FDIM;
    int pad = (LMK - n % LMK) % LMK;
    int N   = n + pad;
    int NB  = N / 128;

    const int SMEM3 = 3*4*8192;   // 96KB
    const int SMEMA = 2*32768;    // 64KB
    cudaFuncSetAttribute(hgemm3<0>, cudaFuncAttributeMaxDynamicSharedMemorySize, SMEM3);
    cudaFuncSetAttribute(hgemm3<1>, cudaFuncAttributeMaxDynamicSharedMemorySize, SMEM3);
    cudaFuncSetAttribute(hgemm3<2>, cudaFuncAttributeMaxDynamicSharedMemorySize, SMEM3);
    cudaFuncSetAttribute(attmma, cudaFuncAttributeMaxDynamicSharedMemorySize, SMEMA);

    float* gb = nullptr;
    cudaGetSymbolAddress((void**)&gb, g_buf);
    float* XN  = gb + OFF_XN;
    float* Q   = gb + OFF_Q;    float* KT  = gb + OFF_KT;
    float* QL  = gb + OFF_QL;   float* KLT = gb + OFF_KLT;
    float* A1  = gb + OFF_A1;   float* A2  = gb + OFF_A2;
    float* A3  = gb + OFF_A3;   float* Z   = gb + OFF_Z;
    float* OC  = gb + OFF_OCAT; float* PRJ = gb + OFF_PROJ;
    __half* H0 = (__half*)(gb + OFF_H16);
    __half *A12f  = H0+H_A12F;
    __half *A3s   = H0+H_A3;
    __half *A1Th  = H0+H_A1T,  *A1Tl = A1Th + HB;
    __half *XNTh  = H0+H_XNT,  *XNTl = XNTh + NP*FDIM;
    __half *WQh   = H0+H_WQ,   *WQl  = WQh + FDIM*768LL;
    __half *ZIh   = H0+H_ZI,   *ZIl  = ZIh + HEADS*LMK*LMK;
    __half *OCTh  = H0+H_OCT,  *OCTl = OCTh + NP*FDIM;
    __half *WOh   = H0+H_WO,   *WOl  = WOh + FDIM*FDIM;

    long long s2 = (long long)LMK*LMK;

    cudaStream_t s1, s2s;
    cudaStreamCreateWithFlags(&s1,  cudaStreamNonBlocking);
    cudaStreamCreateWithFlags(&s2s, cudaStreamNonBlocking);
    cudaEvent_t evRoot, evWQ, evLMK, evA1S, evZI, evAV, evA12, evA3S, evEPI;
    cudaEventCreateWithFlags(&evRoot, cudaEventDisableTiming);
    cudaEventCreateWithFlags(&evWQ,   cudaEventDisableTiming);
    cudaEventCreateWithFlags(&evLMK,  cudaEventDisableTiming);
    cudaEventCreateWithFlags(&evA1S,  cudaEventDisableTiming);
    cudaEventCreateWithFlags(&evZI,   cudaEventDisableTiming);
    cudaEventCreateWithFlags(&evAV,   cudaEventDisableTiming);
    cudaEventCreateWithFlags(&evA12,  cudaEventDisableTiming);
    cudaEventCreateWithFlags(&evA3S,  cudaEventDisableTiming);
    cudaEventCreateWithFlags(&evEPI,  cudaEventDisableTiming);

    cudaEventRecord(evRoot, 0);
    cudaStreamWaitEvent(s1,  evRoot, 0);
    cudaStreamWaitEvent(s2s, evRoot, 0);

    // s1: weight splits
    split_h<<<(int)((FDIM*768LL/4 + 255)/256), 256, 0, s1>>>(w_qkv, WQh, WQl, FDIM*768LL/4);
    cudaEventRecord(evWQ, s1);
    split_h<<<(int)((FDIM*FDIM/4LL + 255)/256), 256, 0, s1>>>(w_out, WOh, WOl, FDIM*FDIM/4LL);

    // 0: LN -> split -> qkv GEMM (fused scatter) -> landmarks
    ln_kernel<<<N, 256>>>(x, ln_g, ln_b, pad);
    splitT_h<<<dim3(N/32, FDIM/32, 1), 256>>>(XN, XNTh, XNTl, N, FDIM);
    cudaStreamWaitEvent(0, evWQ, 0);
    hgemm3<1><<<dim3(6, NB, 1), 256, SMEM3>>>(nullptr, XNTh, XNTl, WQh, WQl, N, 768, 256, 0, 0, 0, nullptr);
    landmarks<<<dim3(LMK/8, HEADS), 256>>>(N);
    cudaEventRecord(evLMK, 0);

    // s2s: A1 scores -> softmax+split
    cudaStreamWaitEvent(s2s, evLMK, 0);
    bgemm128<<<dim3(1, NB, HEADS), 256, 0, s2s>>>(A1, Q, KLT, 128, 32, (long long)N*DH, DH*LMK, (long long)N*LMK);
    softmax_a1_split<<<dim3(N/32, HEADS), 256, 0, s2s>>>(A1, A1Th, A1Tl, N);
    cudaEventRecord(evA1S, s2s);

    // s1: A2 scores -> pinv branch
    cudaStreamWaitEvent(s1, evLMK, 0);
    bgemm128<<<dim3(1, 1, HEADS), 256, 0, s1>>>(A2, QL, KLT, 128, 32, LMK*DH, DH*LMK, s2);
    softmax_rows<1><<<HEADS*LMK, 256, 0, s1>>>(A2, 128);
    colmax_a2<<<HEADS, 128, 0, s1>>>();
    zinit<<<(HEADS*LMK*LMK + 255)/256, 256, 0, s1>>>();
    pinv_fused<<<dim3(4, HEADS), 256, 0, s1>>>();
    split_h<<<(int)((HEADS*s2/4 + 255)/256), 256, 0, s1>>>(Z, ZIh, ZIl, HEADS*s2/4);
    cudaEventRecord(evZI, s1);

    // 0: A3 scores -> softmax (fp16)
    bgemm128<<<dim3(NB, 1, HEADS), 256>>>(A3, QL, KT, N, 32, LMK*DH, (long long)DH*N, (long long)LMK*N);
    softmax_a3<<<HEADS*LMK, 256>>>(A3, A3s, N);
    cudaEventRecord(evA3S, 0);

    // s2s: av branch (after its own A1 work + A3 softmax)
    cudaStreamWaitEvent(s2s, evA3S, 0);
    av_part<<<dim3(AVKC, HEADS), 256, 0, s2s>>>(A3s, N);
    av_reduce<<<(HEADS*LMK*DH + 255)/256, 256, 0, s2s>>>();
    cudaEventRecord(evAV, s2s);

    // 0: a12 GEMM (fp16-only out)
    cudaStreamWaitEvent(0, evA1S, 0);
    cudaStreamWaitEvent(0, evZI, 0);
    hgemm3<2><<<dim3(1, NB, HEADS), 256, SMEM3>>>(nullptr, A1Th, A1Tl, ZIh, ZIl, N, 128, 128,
        (long long)LMK*N, s2, (long long)N*LMK, A12f);
    cudaEventRecord(evA12, 0);

    // s1: output path overlaps attmma
    cudaStreamWaitEvent(s1, evA12, 0);
    cudaStreamWaitEvent(s1, evAV, 0);
    ocat_kernel<<<dim3(NB, HEADS), 128, 0, s1>>>(rk, A12f, N);
    splitT_h<<<dim3(N/32, FDIM/32, 1), 256, 0, s1>>>(OC, OCTh, OCTl, N, FDIM);
    hgemm3<0><<<dim3(2, NB, 1), 256, SMEM3, s1>>>(PRJ, OCTh, OCTl, WOh, WOl, N, 256, 256, 0, 0, 0, nullptr);
    epilogue<<<n, 256, 0, s1>>>(x, b_out, out, pad);
    cudaEventRecord(evEPI, s1);

    // 0: the big att GEMM
    long long base = (long long)n * FDIM;
    attmma<<<dim3(NB, NB, HEADS), 256, SMEMA>>>(out + base, N, A12f, A3s);

    cudaStreamWaitEvent(0, evEPI, 0);
    long long attsz = (long long)HEADS*N*N;
    if ((long long)out_size >= base + attsz + 2)
        tail_k<<<1, 1>>>(out + base + attsz, (float)pad, (float)n);

    cudaStreamCaptureStatus st = cudaStreamCaptureStatusNone;
    cudaStreamIsCapturing(0, &st);
    if (st == cudaStreamCaptureStatusNone) {
        cudaEventDestroy(evRoot); cudaEventDestroy(evWQ); cudaEventDestroy(evLMK);
        cudaEventDestroy(evA1S); cudaEventDestroy(evZI); cudaEventDestroy(evAV);
        cudaEventDestroy(evA12); cudaEventDestroy(evA3S); cudaEventDestroy(evEPI);
        cudaStreamDestroy(s1); cudaStreamDestroy(s2s);
    }
}

// round 13
// speedup vs baseline: 1.5373x; 1.5373x over previous
#include <cuda_runtime.h>
#include <cuda_fp16.h>
#include <cstdint>

#define HEADS 8
#define DH 32
#define LMK 128
#define FDIM 256
#define NP 4096LL

#define OFF_XN   0LL
#define OFF_Q    (OFF_XN + NP*FDIM)
#define OFF_K    (OFF_Q  + HEADS*NP*DH)
#define OFF_V    (OFF_K  + HEADS*NP*DH)
#define OFF_KT   (OFF_V  + HEADS*NP*DH)
#define OFF_QL   (OFF_KT + HEADS*NP*DH)
#define OFF_KLT  (OFF_QL + HEADS*LMK*DH)
#define OFF_A1   (OFF_KLT+ HEADS*DH*LMK)
#define OFF_A2   (OFF_A1 + HEADS*NP*LMK)
#define OFF_A3   (OFF_A2 + HEADS*LMK*LMK)
#define OFF_Z    (OFF_A3 + HEADS*LMK*NP)
#define OFF_Z2   (OFF_Z  + HEADS*LMK*LMK)
#define OFF_AZ   (OFF_Z2 + HEADS*LMK*LMK)
#define OFF_T1   (OFF_AZ + HEADS*LMK*LMK)
#define OFF_T2   (OFF_T1 + HEADS*LMK*LMK)
#define OFF_AV   (OFF_T2 + HEADS*LMK*LMK)
#define OFF_OCAT (OFF_AV + HEADS*LMK*DH)
#define OFF_PROJ (OFF_OCAT+ NP*FDIM)
#define OFF_AVP  (OFF_PROJ+ NP*FDIM)
#define OFF_H16  (OFF_AVP + 16LL*HEADS*LMK*DH)

#define HB  (HEADS*LMK*NP)
#define H_A12F 0LL
#define H_A3   (H_A12F + HB)
#define H_A1T  (H_A3   + HB)
#define H_XNT  (H_A1T  + 2*HB)
#define H_WQ   (H_XNT  + 2*NP*FDIM)
#define H_ZI   (H_WQ   + 2*FDIM*768LL)
#define H_OCT  (H_ZI   + 2*HEADS*LMK*LMK)
#define H_WO   (H_OCT  + 2*NP*FDIM)
#define H_END  (H_WO   + 2*FDIM*FDIM)
#define TOTALF (OFF_H16 + (H_END + 1)/2)

__device__ __align__(128) float g_buf[TOTALF];
__device__ int g_rowmax;

// ---------- LayerNorm + front pad (also zeroes g_rowmax) ----------
__global__ void __launch_bounds__(256) ln_kernel(const float* __restrict__ x,
                                                 const float* __restrict__ g,
                                                 const float* __restrict__ b,
                                                 int pad)
{
    if (blockIdx.x == 0 && threadIdx.x == 0) g_rowmax = 0;
    int r = blockIdx.x, c = threadIdx.x;
    float* xn = g_buf + OFF_XN;
    if (r < pad) { xn[(long long)r*FDIM + c] = 0.f; return; }
    float v = x[(long long)(r - pad)*FDIM + c];
    float s = v, s2 = v*v;
    #pragma unroll
    for (int o = 16; o; o >>= 1) {
        s  += __shfl_xor_sync(0xffffffffu, s,  o);
        s2 += __shfl_xor_sync(0xffffffffu, s2, o);
    }
    __shared__ float ss[8], ss2[8];
    int w = c >> 5;
    if ((c & 31) == 0) { ss[w] = s; ss2[w] = s2; }
    __syncthreads();
    s = 0.f; s2 = 0.f;
    #pragma unroll
    for (int i = 0; i < 8; i++) { s += ss[i]; s2 += ss2[i]; }
    float mean = s * (1.f/256.f);
    float var  = s2 * (1.f/256.f) - mean*mean;
    xn[(long long)r*FDIM + c] = (v - mean) * rsqrtf(var + 1e-5f) * g[c] + b[c];
}

// ---------- fp32 tile GEMM (small K=32 score GEMMs) ----------
__global__ void __launch_bounds__(256, 2) bgemm128(
    float* __restrict__ C, const float* __restrict__ A, const float* __restrict__ B,
    int Ni, int Ki, long long sA, long long sB, long long sC)
{
    A += (long long)blockIdx.z * sA;
    B += (long long)blockIdx.z * sB;
    C += (long long)blockIdx.z * sC;
    const int m0 = blockIdx.y * 128, n0 = blockIdx.x * 128;
    __shared__ float As[8][128];
    __shared__ float Bs[8][128];
    const int tid = threadIdx.x;
    const int tx = tid & 15, ty = tid >> 4;
    float acc[8][8];
    #pragma unroll
    for (int i = 0; i < 8; i++)
        #pragma unroll
        for (int j = 0; j < 8; j++) acc[i][j] = 0.f;
    const int am = tid >> 1, ak = (tid & 1) << 2;
    const int bk = tid >> 5, bn = (tid & 31) << 2;
    for (int k0 = 0; k0 < Ki; k0 += 8) {
        float4 a4 = *(const float4*)(A + (long long)(m0 + am)*Ki + (k0 + ak));
        float4 b4 = *(const float4*)(B + (long long)(k0 + bk)*Ni + (n0 + bn));
        As[ak+0][am] = a4.x; As[ak+1][am] = a4.y; As[ak+2][am] = a4.z; As[ak+3][am] = a4.w;
        *(float4*)&Bs[bk][bn] = b4;
        __syncthreads();
        #pragma unroll
        for (int kk = 0; kk < 8; kk++) {
            float a[8], b[8];
            *(float4*)(a)     = *(const float4*)&As[kk][ty*4];
            *(float4*)(a + 4) = *(const float4*)&As[kk][64 + ty*4];
            *(float4*)(b)     = *(const float4*)&Bs[kk][tx*4];
            *(float4*)(b + 4) = *(const float4*)&Bs[kk][64 + tx*4];
            #pragma unroll
            for (int i = 0; i < 8; i++)
                #pragma unroll
                for (int j = 0; j < 8; j++)
                    acc[i][j] += a[i]*b[j];
        }
        __syncthreads();
    }
    #pragma unroll
    for (int i = 0; i < 8; i++) {
        int m = m0 + ((i >> 2) << 6) + ty*4 + (i & 3);
        #pragma unroll
        for (int jh = 0; jh < 2; jh++) {
            float4 r;
            r.x = acc[i][jh*4+0]; r.y = acc[i][jh*4+1];
            r.z = acc[i][jh*4+2]; r.w = acc[i][jh*4+3];
            *(float4*)(C + (long long)m*Ni + n0 + jh*64 + tx*4) = r;
        }
    }
}

// ---------- fused Newton-Schulz pinv (4-CTA cluster per head) ----------
__device__ __forceinline__ void csync() {
    asm volatile("barrier.cluster.arrive.aligned;" ::: "memory");
    asm volatile("barrier.cluster.wait.aligned;" ::: "memory");
}

__device__ __forceinline__ void gemm64_dev(
    float* __restrict__ C, const float* __restrict__ A, const float* __restrict__ B,
    int m0, int n0, float ids, float es, float alpha,
    float (*As)[64], float (*Bs)[64])
{
    int tid = threadIdx.x;
    int tx = tid & 15, ty = tid >> 4;
    float acc[4][4];
    #pragma unroll
    for (int i = 0; i < 4; i++)
        #pragma unroll
        for (int j = 0; j < 4; j++) acc[i][j] = 0.f;
    int am = tid >> 2, ak = (tid & 3) << 2;
    int bk = tid >> 4, bn = (tid & 15) << 2;
    for (int k0 = 0; k0 < 128; k0 += 16) {
        float4 a4 = *(const float4*)(A + (m0 + am)*128 + k0 + ak);
        float4 b4 = *(const float4*)(B + (k0 + bk)*128 + n0 + bn);
        b4.x *= es; b4.y *= es; b4.z *= es; b4.w *= es;
        int kg = k0 + bk, ng = n0 + bn;
        if      (kg == ng)     b4.x += ids;
        else if (kg == ng + 1) b4.y += ids;
        else if (kg == ng + 2) b4.z += ids;
        else if (kg == ng + 3) b4.w += ids;
        As[ak+0][am] = a4.x; As[ak+1][am] = a4.y; As[ak+2][am] = a4.z; As[ak+3][am] = a4.w;
        *(float4*)&Bs[bk][bn] = b4;
        __syncthreads();
        #pragma unroll
        for (int kk = 0; kk < 16; kk++) {
            float a[4], b[4];
            *(float4*)a = *(const float4*)&As[kk][ty*4];
            *(float4*)b = *(const float4*)&Bs[kk][tx*4];
            #pragma unroll
            for (int i = 0; i < 4; i++)
                #pragma unroll
                for (int j = 0; j < 4; j++) acc[i][j] += a[i]*b[j];
        }
        __syncthreads();
    }
    #pragma unroll
    for (int i = 0; i < 4; i++) {
        float4 r;
        r.x = alpha*acc[i][0]; r.y = alpha*acc[i][1];
        r.z = alpha*acc[i][2]; r.w = alpha*acc[i][3];
        *(float4*)(C + (m0 + ty*4 + i)*128 + n0 + tx*4) = r;
    }
}

__global__ void __cluster_dims__(4,1,1) __launch_bounds__(256) pinv_fused()
{
    __shared__ float As[16][64];
    __shared__ float Bs[16][64];
    int q = blockIdx.x, h = blockIdx.y;
    int m0 = (q >> 1) * 64, n0 = (q & 1) * 64;
    long long s2 = (long long)LMK*LMK;
    float* A2 = g_buf + OFF_A2 + h*s2;
    float* Z  = g_buf + OFF_Z  + h*s2;
    float* Z2 = g_buf + OFF_Z2 + h*s2;
    float* AZ = g_buf + OFF_AZ + h*s2;
    float* T1 = g_buf + OFF_T1 + h*s2;
    float* T2 = g_buf + OFF_T2 + h*s2;
    float* zi = Z; float* zo = Z2;
    #pragma unroll 1
    for (int it = 0; it < 6; it++) {
        gemm64_dev(AZ, A2, zi, m0, n0, 0.f,   1.f, 1.f,   As, Bs); csync();
        gemm64_dev(T1, AZ, AZ, m0, n0, 7.f,  -1.f, 1.f,   As, Bs); csync();
        gemm64_dev(T2, AZ, T1, m0, n0, 15.f, -1.f, 1.f,   As, Bs); csync();
        gemm64_dev(zo, zi, T2, m0, n0, 13.f, -1.f, 0.25f, As, Bs); csync();
        float* t = zi; zi = zo; zo = t;
    }
}

// ---------- landmark means (8 warps / block) ----------
__global__ void __launch_bounds__(256) landmarks(int N)
{
    int h = blockIdx.y;
    int w = threadIdx.x >> 5, lane = threadIdx.x & 31;
    int i = blockIdx.x * 8 + w;
    int l = N / LMK;
    const float* q = g_buf + OFF_Q + ((long long)h*N + (long long)i*l)*DH;
    const float* k = g_buf + OFF_K + ((long long)h*N + (long long)i*l)*DH;
    float sq = 0.f, sk = 0.f;
    for (int r = 0; r < l; r++) { sq += q[r*DH + lane]; sk += k[r*DH + lane]; }
    float inv = 1.f / (float)l;
    g_buf[OFF_QL  + ((long long)h*LMK + i)*DH + lane] = sq * inv;
    g_buf[OFF_KLT + ((long long)h*DH + lane)*LMK + i] = sk * inv;
}

// ---------- generic row softmax (L<=256) ----------
template <int CNT>
__global__ void softmax_rows(float* __restrict__ p, int L)
{
    long long row = blockIdx.x;
    float* r = p + row * (long long)L;
    float v[CNT];
    float mx = -1e30f;
    #pragma unroll
    for (int t = 0; t < CNT; t++) {
        int i = threadIdx.x + t*256;
        v[t] = (i < L) ? r[i] : -1e30f;
        mx = fmaxf(mx, v[t]);
    }
    #pragma unroll
    for (int o = 16; o; o >>= 1) mx = fmaxf(mx, __shfl_xor_sync(0xffffffffu, mx, o));
    __shared__ float sh[8], sh2[8];
    int w = threadIdx.x >> 5;
    if ((threadIdx.x & 31) == 0) sh[w] = mx;
    __syncthreads();
    mx = sh[0];
    #pragma unroll
    for (int i = 1; i < 8; i++) mx = fmaxf(mx, sh[i]);
    float sum = 0.f;
    #pragma unroll
    for (int t = 0; t < CNT; t++) {
        int i = threadIdx.x + t*256;
        if (i < L) { v[t] = __expf(v[t] - mx); sum += v[t]; }
    }
    #pragma unroll
    for (int o = 16; o; o >>= 1) sum += __shfl_xor_sync(0xffffffffu, sum, o);
    if ((threadIdx.x & 31) == 0) sh2[w] = sum;
    __syncthreads();
    sum = 0.f;
    #pragma unroll
    for (int i = 0; i < 8; i++) sum += sh2[i];
    float inv = 1.f / sum;
    #pragma unroll
    for (int t = 0; t < CNT; t++) {
        int i = threadIdx.x + t*256;
        if (i < L) r[i] = v[t] * inv;
    }
}

// ---------- fused softmax(A1) + transpose + fp16 hi/lo split ----------
__global__ void __launch_bounds__(256) softmax_a1_split(
        const float* __restrict__ A1, __half* __restrict__ hi,
        __half* __restrict__ lo, int N)
{
    __shared__ float sm[32][132];
    int h = blockIdx.y, t0 = blockIdx.x * 32;
    const float* base = A1 + ((long long)h*N + t0)*LMK;
    for (int i = threadIdx.x; i < 32*32; i += 256) {
        int r = i >> 5, c4 = (i & 31) << 2;
        *(float4*)&sm[r][c4] = *(const float4*)(base + r*LMK + c4);
    }
    __syncthreads();
    int w = threadIdx.x >> 5, lane = threadIdx.x & 31;
    #pragma unroll
    for (int j = 0; j < 4; j++) {
        int r = w*4 + j;
        float v0 = sm[r][lane], v1 = sm[r][lane+32], v2 = sm[r][lane+64], v3 = sm[r][lane+96];
        float mx = fmaxf(fmaxf(v0, v1), fmaxf(v2, v3));
        #pragma unroll
        for (int o = 16; o; o >>= 1) mx = fmaxf(mx, __shfl_xor_sync(0xffffffffu, mx, o));
        v0 = __expf(v0 - mx); v1 = __expf(v1 - mx); v2 = __expf(v2 - mx); v3 = __expf(v3 - mx);
        float s = v0 + v1 + v2 + v3;
        #pragma unroll
        for (int o = 16; o; o >>= 1) s += __shfl_xor_sync(0xffffffffu, s, o);
        float inv = 1.f / s;
        sm[r][lane] = v0*inv; sm[r][lane+32] = v1*inv;
        sm[r][lane+64] = v2*inv; sm[r][lane+96] = v3*inv;
    }
    __syncthreads();
    #pragma unroll
    for (int j = 0; j < 16; j++) {
        int k = w*16 + j;
        float v = sm[lane][k];
        __half hv = __float2half(v);
        __half lv = __float2half(v - __half2float(hv));
        long long o = ((long long)h*LMK + k)*N + t0 + lane;
        hi[o] = hv; lo[o] = lv;
    }
}

// ---------- A3 softmax (L = N), emits fp16 ONLY ----------
__global__ void __launch_bounds__(256) softmax_a3(const float* __restrict__ p,
                                                  __half* __restrict__ ph, int L)
{
    long long row = blockIdx.x;
    const float* r = p + row * (long long)L;
    __half* rh = ph + row * (long long)L;
    float v[16];
    float mx = -1e30f;
    #pragma unroll
    for (int t = 0; t < 16; t++) {
        int i = threadIdx.x + t*256;
        v[t] = r[i];
        mx = fmaxf(mx, v[t]);
    }
    #pragma unroll
    for (int o = 16; o; o >>= 1) mx = fmaxf(mx, __shfl_xor_sync(0xffffffffu, mx, o));
    __shared__ float sh[8], sh2[8];
    int w = threadIdx.x >> 5;
    if ((threadIdx.x & 31) == 0) sh[w] = mx;
    __syncthreads();
    mx = sh[0];
    #pragma unroll
    for (int i = 1; i < 8; i++) mx = fmaxf(mx, sh[i]);
    float sum = 0.f;
    #pragma unroll
    for (int t = 0; t < 16; t++) { v[t] = __expf(v[t] - mx); sum += v[t]; }
    #pragma unroll
    for (int o = 16; o; o >>= 1) sum += __shfl_xor_sync(0xffffffffu, sum, o);
    if ((threadIdx.x & 31) == 0) sh2[w] = sum;
    __syncthreads();
    sum = 0.f;
    #pragma unroll
    for (int i = 0; i < 8; i++) sum += sh2[i];
    float inv = 1.f / sum;
    #pragma unroll
    for (int t = 0; t < 16; t++) {
        int i = threadIdx.x + t*256;
        rh[i] = __float2half(v[t] * inv);
    }
}

// ---------- pinv norm ----------
__global__ void colmax_a2()
{
    int h = blockIdx.x, j = threadIdx.x;
    const float* a = g_buf + OFF_A2 + (long long)h*LMK*LMK;
    float s = 0.f;
    for (int i = 0; i < LMK; i++) s += a[i*LMK + j];
    #pragma unroll
    for (int o = 16; o; o >>= 1) s = fmaxf(s, __shfl_xor_sync(0xffffffffu, s, o));
    __shared__ float sh[4];
    if ((j & 31) == 0) sh[j >> 5] = s;
    __syncthreads();
    if (j == 0) {
        s = fmaxf(fmaxf(sh[0], sh[1]), fmaxf(sh[2], sh[3]));
        atomicMax(&g_rowmax, __float_as_int(s));
    }
}

__global__ void zinit()
{
    long long idx = (long long)blockIdx.x * 256 + threadIdx.x;
    if (idx >= (long long)HEADS*LMK*LMK) return;
    int h = (int)(idx >> 14), rem = (int)(idx & 16383);
    int i = rem >> 7, j = rem & 127;
    float row = __int_as_float(g_rowmax);
    g_buf[OFF_Z + idx] = g_buf[OFF_A2 + ((long long)h*LMK + j)*LMK + i] / row;
}

// ---------- av = attn3(fp16) @ v, split-K ----------
#define AVKC 16
__global__ void __launch_bounds__(256) av_part(const __half* __restrict__ A3h, int N)
{
    int kc = blockIdx.x, h = blockIdx.y;
    const int KLEN = N / AVKC;
    __shared__ float vs[256*32];
    const float* vh = g_buf + OFF_V + ((long long)h*N + (long long)kc*KLEN)*DH;
    for (int i = threadIdx.x; i < KLEN*DH/4; i += 256)
        ((float4*)vs)[i] = ((const float4*)vh)[i];
    __syncthreads();
    int warp = threadIdx.x >> 5, lane = threadIdx.x & 31;
    for (int r = warp; r < LMK; r += 8) {
        const __half* arow = A3h + ((long long)h*LMK + r)*N + kc*KLEN;
        float acc = 0.f;
        #pragma unroll 2
        for (int k = 0; k < KLEN; k += 8) {
            __half2 a01 = *(const __half2*)(arow + k);
            __half2 a23 = *(const __half2*)(arow + k + 2);
            __half2 a45 = *(const __half2*)(arow + k + 4);
            __half2 a67 = *(const __half2*)(arow + k + 6);
            float2 f01 = __half22float2(a01), f23 = __half22float2(a23);
            float2 f45 = __half22float2(a45), f67 = __half22float2(a67);
            acc += f01.x * vs[(k+0)*DH + lane] + f01.y * vs[(k+1)*DH + lane];
            acc += f23.x * vs[(k+2)*DH + lane] + f23.y * vs[(k+3)*DH + lane];
            acc += f45.x * vs[(k+4)*DH + lane] + f45.y * vs[(k+5)*DH + lane];
            acc += f67.x * vs[(k+6)*DH + lane] + f67.y * vs[(k+7)*DH + lane];
        }
        g_buf[OFF_AVP + ((long long)kc*HEADS*LMK + (long long)h*LMK + r)*DH + lane] = acc;
    }
}
__global__ void av_reduce()
{
    int idx = blockIdx.x*256 + threadIdx.x;
    if (idx >= HEADS*LMK*DH) return;
    float s = 0.f;
    #pragma unroll
    for (int kc = 0; kc < AVKC; kc++)
        s += g_buf[OFF_AVP + (long long)kc*HEADS*LMK*DH + idx];
    g_buf[OFF_AV + idx] = s;
}

// ---------- ocat = concat_h( a12(fp16) @ av + depthwise_conv(v) ) ----------
__global__ void __launch_bounds__(128) ocat_kernel(const float* __restrict__ rk,
                                                   const __half* __restrict__ A12f, int N)
{
    int h = blockIdx.y, tid = threadIdx.x;
    int t = blockIdx.x * 128 + tid;
    __shared__ float avs[LMK][32];
    __shared__ float kr[33];
    const float* av = g_buf + OFF_AV + (long long)h*LMK*DH;
    #pragma unroll
    for (int c4 = 0; c4 < 8; c4++)
        *(float4*)&avs[tid][c4*4] = *(const float4*)(av + tid*DH + c4*4);
    if (tid < 33) kr[tid] = rk[h*33 + tid];
    __syncthreads();
    const __half* a12row = A12f + ((long long)h*N + t)*LMK;
    float acc[32];
    #pragma unroll
    for (int c = 0; c < 32; c++) acc[c] = 0.f;
    for (int k = 0; k < LMK; k += 2) {
        __half2 a2 = *(const __half2*)(a12row + k);
        float2 af = __half22float2(a2);
        #pragma unroll
        for (int c = 0; c < 32; c++) acc[c] += af.x * avs[k][c] + af.y * avs[k+1][c];
    }
    const float* vh = g_buf + OFF_V + (long long)h*N*DH;
    for (int j = 0; j < 33; j++) {
        int tt = t + j - 16;
        if (tt >= 0 && tt < N) {
            float w = kr[j];
            const float4* vr = (const float4*)(vh + (long long)tt*DH);
            #pragma unroll
            for (int c4 = 0; c4 < 8; c4++) {
                float4 vv = vr[c4];
                acc[c4*4+0] += w*vv.x; acc[c4*4+1] += w*vv.y;
                acc[c4*4+2] += w*vv.z; acc[c4*4+3] += w*vv.w;
            }
        }
    }
    float* o = g_buf + OFF_OCAT + (long long)t*FDIM + h*DH;
    #pragma unroll
    for (int c4 = 0; c4 < 8; c4++)
        *(float4*)(o + c4*4) = make_float4(acc[c4*4], acc[c4*4+1], acc[c4*4+2], acc[c4*4+3]);
}

// ---------- final residual epilogue ----------
__global__ void epilogue(const float* __restrict__ x, const float* __restrict__ b_out,
                         float* __restrict__ out, int pad)
{
    int t = blockIdx.x, c = threadIdx.x;
    long long i = (long long)t*FDIM + c;
    out[i] = x[i] + g_buf[OFF_PROJ + (long long)(t + pad)*FDIM + c] + b_out[c];
}

__global__ void tail_k(float* p, float a, float b) { p[0] = a; p[1] = b; }

// ============= fp16 prep kernels =============
__global__ void __launch_bounds__(256) split_h(const float* __restrict__ src,
                                               __half* __restrict__ hi,
                                               __half* __restrict__ lo,
                                               long long total4)
{
    long long i = (long long)blockIdx.x*256 + threadIdx.x;
    if (i >= total4) return;
    float4 v = ((const float4*)src)[i];
    __half h0 = __float2half(v.x), h1 = __float2half(v.y);
    __half h2 = __float2half(v.z), h3 = __float2half(v.w);
    __half l0 = __float2half(v.x - __half2float(h0));
    __half l1 = __float2half(v.y - __half2float(h1));
    __half l2 = __float2half(v.z - __half2float(h2));
    __half l3 = __float2half(v.w - __half2float(h3));
    ((ushort4*)hi)[i] = make_ushort4(__half_as_ushort(h0), __half_as_ushort(h1),
                                     __half_as_ushort(h2), __half_as_ushort(h3));
    ((ushort4*)lo)[i] = make_ushort4(__half_as_ushort(l0), __half_as_ushort(l1),
                                     __half_as_ushort(l2), __half_as_ushort(l3));
}

__global__ void __launch_bounds__(256) splitT_h(const float* __restrict__ src,
                                                __half* __restrict__ hi,
                                                __half* __restrict__ lo,
                                                int M, int K)
{
    __shared__ float t[32][33];
    long long bs = (long long)blockIdx.z * M * K;
    int m0 = blockIdx.x * 32, k0 = blockIdx.y * 32;
    int tx = threadIdx.x & 31, ty = threadIdx.x >> 5;
    #pragma unroll
    for (int j = 0; j < 4; j++) {
        int ml = ty + 8*j;
        t[ml][tx] = src[bs + (long long)(m0 + ml)*K + k0 + tx];
    }
    __syncthreads();
    #pragma unroll
    for (int j = 0; j < 4; j++) {
        int kl = ty + 8*j;
        float v = t[tx][kl];
        __half hv = __float2half(v);
        __half lv = __float2half(v - __half2float(hv));
        long long o = bs + (long long)(k0 + kl)*M + m0 + tx;
        hi[o] = hv; lo[o] = lv;
    }
}

// ============= mma helpers =============
__device__ __forceinline__ void ldsm4(uint32_t* r, uint32_t addr) {
    asm volatile("ldmatrix.sync.aligned.m8n8.x4.shared.b16 {%0,%1,%2,%3}, [%4];"
        : "=r"(r[0]), "=r"(r[1]), "=r"(r[2]), "=r"(r[3]) : "r"(addr));
}
__device__ __forceinline__ void ldsm4t(uint32_t* r, uint32_t addr) {
    asm volatile("ldmatrix.sync.aligned.m8n8.x4.trans.shared.b16 {%0,%1,%2,%3}, [%4];"
        : "=r"(r[0]), "=r"(r[1]), "=r"(r[2]), "=r"(r[3]) : "r"(addr));
}
__device__ __forceinline__ void mma16816(float* c, const uint32_t* a, const uint32_t* b) {
    asm volatile("mma.sync.aligned.m16n8k16.row.col.f32.f16.f16.f32 "
        "{%0,%1,%2,%3}, {%4,%5,%6,%7}, {%8,%9}, {%0,%1,%2,%3};"
        : "+f"(c[0]), "+f"(c[1]), "+f"(c[2]), "+f"(c[3])
        : "r"(a[0]), "r"(a[1]), "r"(a[2]), "r"(a[3]), "r"(b[0]), "r"(b[1]));
}
__device__ __forceinline__ void cpasync16(uint32_t saddr, const void* gaddr) {
    asm volatile("cp.async.cg.shared.global [%0], [%1], 16;\n" :: "r"(saddr), "l"(gaddr));
}
__device__ __forceinline__ void cpcommit() { asm volatile("cp.async.commit_group;\n"); }
template <int NN>
__device__ __forceinline__ void cpwait() { asm volatile("cp.async.wait_group %0;\n" :: "n"(NN)); }
__device__ __forceinline__ void stcs2(float* p, float x, float y) {
    asm volatile("st.global.cs.v2.f32 [%0], {%1,%2};" :: "l"(p), "f"(x), "f"(y) : "memory");
}

// ============= pipelined fp16 3-prod GEMM, templated epilogue =============
// EPI 0: write fp32 C (+ optional fp16 Ch)
// EPI 1: qkv scatter: write Q(scaled)/K/KT/V directly (ldA = token count)
// EPI 2: write ONLY fp16 Ch
template <int EPI>
__global__ void __launch_bounds__(256, 2) hgemm3(float* __restrict__ C,
        const __half* __restrict__ Ah, const __half* __restrict__ Al,
        const __half* __restrict__ Bh, const __half* __restrict__ Bl,
        int ldA, int N, int K, long long sA, long long sB, long long sC,
        __half* __restrict__ Ch)
{
    constexpr int D = 3;
    Ah += (long long)blockIdx.z * sA;  Al += (long long)blockIdx.z * sA;
    Bh += (long long)blockIdx.z * sB;  Bl += (long long)blockIdx.z * sB;
    if (EPI == 0) C  += (long long)blockIdx.z * sC;
    if (Ch) Ch += (long long)blockIdx.z * sC;
    const int m0 = blockIdx.y * 128, n0 = blockIdx.x * 128;

    extern __shared__ __align__(16) uint8_t dsm[];
    const uint32_t sb = (uint32_t)__cvta_generic_to_shared(dsm);
    const int tid = threadIdx.x, lane = tid & 31, warp = tid >> 5;
    const int wm = warp >> 1, wn = warp & 1;

    const int T = K >> 5;
    int li0 = tid, li1 = tid + 256;
    int lk0 = li0 >> 4, ls0 = li0 & 15;
    int lk1 = li1 >> 4, ls1 = li1 & 15;
    uint32_t d0 = (uint32_t)(lk0*256 + ((ls0 ^ (lk0 & 7)) << 4));
    uint32_t d1 = (uint32_t)(lk1*256 + ((ls1 ^ (lk1 & 7)) << 4));

    auto load_stage = [&](int stage, int chunk) {
        int kb = chunk << 5;
        uint32_t s0 = sb + (uint32_t)(stage*4) * 8192u;
        long long ga0 = (long long)(kb + lk0)*ldA + m0 + ls0*8;
        long long ga1 = (long long)(kb + lk1)*ldA + m0 + ls1*8;
        long long gb0 = (long long)(kb + lk0)*N   + n0 + ls0*8;
        long long gb1 = (long long)(kb + lk1)*N   + n0 + ls1*8;
        cpasync16(s0 +         d0, Ah + ga0);  cpasync16(s0 +         d1, Ah + ga1);
        cpasync16(s0 +  8192 + d0, Al + ga0);  cpasync16(s0 +  8192 + d1, Al + ga1);
        cpasync16(s0 + 16384 + d0, Bh + gb0);  cpasync16(s0 + 16384 + d1, Bh + gb1);
        cpasync16(s0 + 24576 + d0, Bl + gb0);  cpasync16(s0 + 24576 + d1, Bl + gb1);
    };

    float acc[2][8][4];
    #pragma unroll
    for (int i = 0; i < 2; i++)
        #pragma unroll
        for (int j = 0; j < 8; j++)
            #pragma unroll
            for (int q = 0; q < 4; q++) acc[i][j][q] = 0.f;

    #pragma unroll
    for (int s = 0; s < D-1; s++) {
        if (s < T) load_stage(s, s);
        cpcommit();
    }

    for (int it = 0; it < T; it++) {
        cpwait<D-2>();
        __syncthreads();
        int st = it % D;
        uint32_t sA0 = sb + (uint32_t)(st*4) * 8192u;

        #pragma unroll
        for (int ks = 0; ks < 32; ks += 16) {
            uint32_t ah[2][4], al[2][4];
            #pragma unroll
            for (int mt = 0; mt < 2; mt++) {
                int kr  = ks + (lane & 7) + ((lane >> 4) << 3);
                int seg = (wm*4 + mt*2) + ((lane >> 3) & 1);
                uint32_t a = (uint32_t)(kr*256 + ((seg ^ (kr & 7)) << 4));
                ldsm4t(ah[mt], sA0 + a);
                ldsm4t(al[mt], sA0 + 8192 + a);
            }
            #pragma unroll
            for (int np = 0; np < 4; np++) {
                int kr  = ks + (lane & 7) + (((lane >> 3) & 1) << 3);
                int seg = (wn*8 + np*2) + ((lane >> 4) & 1);
                uint32_t a = (uint32_t)(kr*256 + ((seg ^ (kr & 7)) << 4));
                uint32_t bh[4], bl[4];
                ldsm4t(bh, sA0 + 16384 + a);
                ldsm4t(bl, sA0 + 24576 + a);
                #pragma unroll
                for (int mt = 0; mt < 2; mt++) {
                    mma16816(acc[mt][np*2+0], ah[mt], bh + 0);
                    mma16816(acc[mt][np*2+0], al[mt], bh + 0);
                    mma16816(acc[mt][np*2+0], ah[mt], bl + 0);
                    mma16816(acc[mt][np*2+1], ah[mt], bh + 2);
                    mma16816(acc[mt][np*2+1], al[mt], bh + 2);
                    mma16816(acc[mt][np*2+1], ah[mt], bl + 2);
                }
            }
        }
        int nx = it + D - 1;
        if (nx < T) load_stage(nx % D, nx);
        cpcommit();
    }

    const int g = lane >> 2, t4 = lane & 3;
    #pragma unroll
    for (int mt = 0; mt < 2; mt++) {
        int mb = m0 + wm*32 + mt*16 + g;
        #pragma unroll
        for (int nt = 0; nt < 8; nt++) {
            int n = n0 + wn*64 + nt*8 + t4*2;
            #pragma unroll
            for (int half = 0; half < 2; half++) {
                int m = mb + half*8;
                float vx = acc[mt][nt][half*2+0], vy = acc[mt][nt][half*2+1];
                if (EPI == 1) {
                    int which = n >> 8, inner = n & 255;
                    int hh = inner >> 5, dd = inner & 31;
                    long long o = ((long long)hh*ldA + m)*DH + dd;
                    if (which == 0) {
                        g_buf[OFF_Q + o]   = vx * 0.17677669529663688f;
                        g_buf[OFF_Q + o+1] = vy * 0.17677669529663688f;
                    } else if (which == 1) {
                        g_buf[OFF_K + o]   = vx;
                        g_buf[OFF_K + o+1] = vy;
                        g_buf[OFF_KT + ((long long)hh*DH + dd)*ldA + m]     = vx;
                        g_buf[OFF_KT + ((long long)hh*DH + dd + 1)*ldA + m] = vy;
                    } else {
                        g_buf[OFF_V + o]   = vx;
                        g_buf[OFF_V + o+1] = vy;
                    }
                } else {
                    if (EPI == 0)
                        *(float2*)(C + (long long)m*N + n) = make_float2(vx, vy);
                    if (Ch)
                        *(__half2*)(Ch + (long long)m*N + n) = __floats2half2_rn(vx, vy);
                }
            }
        }
    }
}

// ============= att = a12 @ attn3 : A row-major, 2-chunk pipeline =============
__global__ void __launch_bounds__(256, 2) attmma(float* __restrict__ out, int N,
        const __half* __restrict__ A, const __half* __restrict__ B)
{
    const int h = blockIdx.z;
    A += (long long)h * N * LMK;
    B += (long long)h * LMK * N;
    out += (long long)h * N * N;
    const int m0 = blockIdx.y * 128, n0 = blockIdx.x * 128;

    extern __shared__ __align__(16) uint8_t dsm[];
    const uint32_t sb = (uint32_t)__cvta_generic_to_shared(dsm);
    const int tid = threadIdx.x, lane = tid & 31, warp = tid >> 5;
    const int wm = warp >> 1, wn = warp & 1;

    #pragma unroll
    for (int rep = 0; rep < 4; rep++) {
        int i = tid + rep*256;
        int r = i >> 3, s = i & 7;
        uint32_t dA = (uint32_t)(r*256 + ((s ^ (r & 7)) << 4));
        cpasync16(sb + dA, A + (long long)(m0 + r)*LMK + s*8);
    }
    #pragma unroll
    for (int rep = 0; rep < 4; rep++) {
        int i = tid + rep*256;
        int k = i >> 4, s = i & 15;
        uint32_t dB = (uint32_t)(k*256 + ((s ^ (k & 7)) << 4));
        cpasync16(sb + 32768 + dB, B + (long long)k*N + n0 + s*8);
    }
    cpcommit();
    #pragma unroll
    for (int rep = 0; rep < 4; rep++) {
        int i = tid + rep*256;
        int r = i >> 3, s = 8 + (i & 7);
        uint32_t dA = (uint32_t)(r*256 + ((s ^ (r & 7)) << 4));
        cpasync16(sb + dA, A + (long long)(m0 + r)*LMK + s*8);
    }
    #pragma unroll
    for (int rep = 0; rep < 4; rep++) {
        int i = tid + rep*256;
        int k = 64 + (i >> 4), s = i & 15;
        uint32_t dB = (uint32_t)(k*256 + ((s ^ (k & 7)) << 4));
        cpasync16(sb + 32768 + dB, B + (long long)k*N + n0 + s*8);
    }
    cpcommit();

    float acc[2][8][4];
    #pragma unroll
    for (int i = 0; i < 2; i++)
        #pragma unroll
        for (int j = 0; j < 8; j++)
            #pragma unroll
            for (int q = 0; q < 4; q++) acc[i][j][q] = 0.f;

    cpwait<1>();
    __syncthreads();

    #pragma unroll 1
    for (int half = 0; half < 2; half++) {
        if (half == 1) { cpwait<0>(); __syncthreads(); }
        #pragma unroll
        for (int ks = half*64; ks < half*64 + 64; ks += 16) {
            uint32_t ah[2][4];
            #pragma unroll
            for (int mt = 0; mt < 2; mt++) {
                int r   = wm*32 + mt*16 + (lane & 7) + ((lane >> 3) & 1)*8;
                int seg = (ks >> 3) + ((lane >> 4) & 1);
                uint32_t a = (uint32_t)(r*256 + ((seg ^ (r & 7)) << 4));
                ldsm4(ah[mt], sb + a);
            }
            #pragma unroll
            for (int np = 0; np < 4; np++) {
                int kr  = ks + (lane & 7) + (((lane >> 3) & 1) << 3);
                int seg = (wn*8 + np*2) + ((lane >> 4) & 1);
                uint32_t a = (uint32_t)(kr*256 + ((seg ^ (kr & 7)) << 4));
                uint32_t bh[4];
                ldsm4t(bh, sb + 32768 + a);
                #pragma unroll
                for (int mt = 0; mt < 2; mt++) {
                    mma16816(acc[mt][np*2+0], ah[mt], bh + 0);
                    mma16816(acc[mt][np*2+1], ah[mt], bh + 2);
                }
            }
        }
    }

    const int g = lane >> 2, t4 = lane & 3;
    #pragma unroll
    for (int mt = 0; mt < 2; mt++) {
        int m = m0 + wm*32 + mt*16 + g;
        #pragma unroll
        for (int nt = 0; nt < 8; nt++) {
            int n = n0 + wn*64 + nt*8 + t4*2;
            stcs2(out + (long long)m*N + n,     acc[mt][nt][0], acc[mt][nt][1]);
            stcs2(out + (long long)(m+8)*N + n, acc[mt][nt][2], acc[mt][nt][3]);
        }
    }
}

// =======================================================================
extern "C" void kernel_launch(void* const* d_in, const int* in_sizes, int n_in,
                              void* d_out, int out_size)
{
    const float* x     = (const float*)d_in[0];
    const float* ln_g  = (const float*)d_in[1];
    const float* ln_b  = (const float*)d_in[2];
    const float* w_qkv = (const float*)d_in[3];
    const float* w_out = (const float*)d_in[4];
    const float* b_out = (const float*)d_in[5];
    const float* rk    = (const float*)d_in[6];
    float* out = (float*)d_out;

    int n   = in_sizes[0] / FDIM;
    int pad = (LMK - n % LMK) % LMK;
    int N   = n + pad;
    int NB  = N / 128;

    const int SMEM3 = 3*4*8192;   // 96KB
    const int SMEMA = 2*32768;    // 64KB
    cudaFuncSetAttribute(hgemm3<0>, cudaFuncAttributeMaxDynamicSharedMemorySize, SMEM3);
    cudaFuncSetAttribute(hgemm3<1>, cudaFuncAttributeMaxDynamicSharedMemorySize, SMEM3);
    cudaFuncSetAttribute(hgemm3<2>, cudaFuncAttributeMaxDynamicSharedMemorySize, SMEM3);
    cudaFuncSetAttribute(attmma, cudaFuncAttributeMaxDynamicSharedMemorySize, SMEMA);

    float* gb = nullptr;
    cudaGetSymbolAddress((void**)&gb, g_buf);
    float* XN  = gb + OFF_XN;
    float* Q   = gb + OFF_Q;    float* KT  = gb + OFF_KT;
    float* QL  = gb + OFF_QL;   float* KLT = gb + OFF_KLT;
    float* A1  = gb + OFF_A1;   float* A2  = gb + OFF_A2;
    float* A3  = gb + OFF_A3;   float* Z   = gb + OFF_Z;
    float* OC  = gb + OFF_OCAT; float* PRJ = gb + OFF_PROJ;
    __half* H0 = (__half*)(gb + OFF_H16);
    __half *A12f  = H0+H_A12F;
    __half *A3s   = H0+H_A3;
    __half *A1Th  = H0+H_A1T,  *A1Tl = A1Th + HB;
    __half *XNTh  = H0+H_XNT,  *XNTl = XNTh + NP*FDIM;
    __half *WQh   = H0+H_WQ,   *WQl  = WQh + FDIM*768LL;
    __half *ZIh   = H0+H_ZI,   *ZIl  = ZIh + HEADS*LMK*LMK;
    __half *OCTh  = H0+H_OCT,  *OCTl = OCTh + NP*FDIM;
    __half *WOh   = H0+H_WO,   *WOl  = WOh + FDIM*FDIM;

    long long s2 = (long long)LMK*LMK;

    cudaStream_t s1, s2s;
    cudaStreamCreateWithFlags(&s1,  cudaStreamNonBlocking);
    cudaStreamCreateWithFlags(&s2s, cudaStreamNonBlocking);
    cudaEvent_t evRoot, evWQ, evLMK, evA1S, evZI, evAV, evA12, evA3S, evEPI;
    cudaEventCreateWithFlags(&evRoot, cudaEventDisableTiming);
    cudaEventCreateWithFlags(&evWQ,   cudaEventDisableTiming);
    cudaEventCreateWithFlags(&evLMK,  cudaEventDisableTiming);
    cudaEventCreateWithFlags(&evA1S,  cudaEventDisableTiming);
    cudaEventCreateWithFlags(&evZI,   cudaEventDisableTiming);
    cudaEventCreateWithFlags(&evAV,   cudaEventDisableTiming);
    cudaEventCreateWithFlags(&evA12,  cudaEventDisableTiming);
    cudaEventCreateWithFlags(&evA3S,  cudaEventDisableTiming);
    cudaEventCreateWithFlags(&evEPI,  cudaEventDisableTiming);

    cudaEventRecord(evRoot, 0);
    cudaStreamWaitEvent(s1,  evRoot, 0);
    cudaStreamWaitEvent(s2s, evRoot, 0);

    // s1: weight splits
    split_h<<<(int)((FDIM*768LL/4 + 255)/256), 256, 0, s1>>>(w_qkv, WQh, WQl, FDIM*768LL/4);
    cudaEventRecord(evWQ, s1);
    split_h<<<(int)((FDIM*FDIM/4LL + 255)/256), 256, 0, s1>>>(w_out, WOh, WOl, FDIM*FDIM/4LL);

    // 0: LN -> split -> qkv GEMM (fused scatter) -> landmarks
    ln_kernel<<<N, 256>>>(x, ln_g, ln_b, pad);
    splitT_h<<<dim3(N/32, FDIM/32, 1), 256>>>(XN, XNTh, XNTl, N, FDIM);
    cudaStreamWaitEvent(0, evWQ, 0);
    hgemm3<1><<<dim3(6, NB, 1), 256, SMEM3>>>(nullptr, XNTh, XNTl, WQh, WQl, N, 768, 256, 0, 0, 0, nullptr);
    landmarks<<<dim3(LMK/8, HEADS), 256>>>(N);
    cudaEventRecord(evLMK, 0);

    // s2s: A1 scores -> softmax+split
    cudaStreamWaitEvent(s2s, evLMK, 0);
    bgemm128<<<dim3(1, NB, HEADS), 256, 0, s2s>>>(A1, Q, KLT, 128, 32, (long long)N*DH, DH*LMK, (long long)N*LMK);
    softmax_a1_split<<<dim3(N/32, HEADS), 256, 0, s2s>>>(A1, A1Th, A1Tl, N);
    cudaEventRecord(evA1S, s2s);

    // s1: A2 scores -> pinv branch
    cudaStreamWaitEvent(s1, evLMK, 0);
    bgemm128<<<dim3(1, 1, HEADS), 256, 0, s1>>>(A2, QL, KLT, 128, 32, LMK*DH, DH*LMK, s2);
    softmax_rows<1><<<HEADS*LMK, 256, 0, s1>>>(A2, 128);
    colmax_a2<<<HEADS, 128, 0, s1>>>();
    zinit<<<(HEADS*LMK*LMK + 255)/256, 256, 0, s1>>>();
    pinv_fused<<<dim3(4, HEADS), 256, 0, s1>>>();
    split_h<<<(int)((HEADS*s2/4 + 255)/256), 256, 0, s1>>>(Z, ZIh, ZIl, HEADS*s2/4);
    cudaEventRecord(evZI, s1);

    // 0: A3 scores -> softmax (fp16)
    bgemm128<<<dim3(NB, 1, HEADS), 256>>>(A3, QL, KT, N, 32, LMK*DH, (long long)DH*N, (long long)LMK*N);
    softmax_a3<<<HEADS*LMK, 256>>>(A3, A3s, N);
    cudaEventRecord(evA3S, 0);

    // s2s: av branch (after its own A1 work + A3 softmax)
    cudaStreamWaitEvent(s2s, evA3S, 0);
    av_part<<<dim3(AVKC, HEADS), 256, 0, s2s>>>(A3s, N);
    av_reduce<<<(HEADS*LMK*DH + 255)/256, 256, 0, s2s>>>();
    cudaEventRecord(evAV, s2s);

    // 0: a12 GEMM (fp16-only out)
    cudaStreamWaitEvent(0, evA1S, 0);
    cudaStreamWaitEvent(0, evZI, 0);
    hgemm3<2><<<dim3(1, NB, HEADS), 256, SMEM3>>>(nullptr, A1Th, A1Tl, ZIh, ZIl, N, 128, 128,
        (long long)LMK*N, s2, (long long)N*LMK, A12f);
    cudaEventRecord(evA12, 0);

    // s1: output path overlaps attmma
    cudaStreamWaitEvent(s1, evA12, 0);
    cudaStreamWaitEvent(s1, evAV, 0);
    ocat_kernel<<<dim3(NB, HEADS), 128, 0, s1>>>(rk, A12f, N);
    splitT_h<<<dim3(N/32, FDIM/32, 1), 256, 0, s1>>>(OC, OCTh, OCTl, N, FDIM);
    hgemm3<0><<<dim3(2, NB, 1), 256, SMEM3, s1>>>(PRJ, OCTh, OCTl, WOh, WOl, N, 256, 256, 0, 0, 0, nullptr);
    epilogue<<<n, 256, 0, s1>>>(x, b_out, out, pad);
    cudaEventRecord(evEPI, s1);

    // 0: the big att GEMM
    long long base = (long long)n * FDIM;
    attmma<<<dim3(NB, NB, HEADS), 256, SMEMA>>>(out + base, N, A12f, A3s);

    cudaStreamWaitEvent(0, evEPI, 0);
    long long attsz = (long long)HEADS*N*N;
    if ((long long)out_size >= base + attsz + 2)
        tail_k<<<1, 1>>>(out + base + attsz, (float)pad, (float)n);

    cudaStreamCaptureStatus st = cudaStreamCaptureStatusNone;
    cudaStreamIsCapturing(0, &st);
    if (st == cudaStreamCaptureStatusNone) {
        cudaEventDestroy(evRoot); cudaEventDestroy(evWQ); cudaEventDestroy(evLMK);
        cudaEventDestroy(evA1S); cudaEventDestroy(evZI); cudaEventDestroy(evAV);
        cudaEventDestroy(evA12); cudaEventDestroy(evA3S); cudaEventDestroy(evEPI);
        cudaStreamDestroy(s1); cudaStreamDestroy(s2s);
    }
}

// round 14
// speedup vs baseline: 1.5375x; 1.0001x over previous
#include <cuda_runtime.h>
#include <cuda_fp16.h>
#include <cstdint>

#define HEADS 8
#define DH 32
#define LMK 128
#define FDIM 256
#define NP 4096LL

#define OFF_XN   0LL
#define OFF_Q    (OFF_XN + NP*FDIM)
#define OFF_K    (OFF_Q  + HEADS*NP*DH)
#define OFF_V    (OFF_K  + HEADS*NP*DH)
#define OFF_KT   (OFF_V  + HEADS*NP*DH)
#define OFF_QL   (OFF_KT + HEADS*NP*DH)
#define OFF_KLT  (OFF_QL + HEADS*LMK*DH)
#define OFF_A1   (OFF_KLT+ HEADS*DH*LMK)
#define OFF_A2   (OFF_A1 + HEADS*NP*LMK)
#define OFF_A3   (OFF_A2 + HEADS*LMK*LMK)
#define OFF_Z    (OFF_A3 + HEADS*LMK*NP)
#define OFF_Z2   (OFF_Z  + HEADS*LMK*LMK)
#define OFF_AZ   (OFF_Z2 + HEADS*LMK*LMK)
#define OFF_T1   (OFF_AZ + HEADS*LMK*LMK)
#define OFF_T2   (OFF_T1 + HEADS*LMK*LMK)
#define OFF_AV   (OFF_T2 + HEADS*LMK*LMK)
#define OFF_OCAT (OFF_AV + HEADS*LMK*DH)
#define OFF_PROJ (OFF_OCAT+ NP*FDIM)
#define OFF_AVP  (OFF_PROJ+ NP*FDIM)
#define OFF_H16  (OFF_AVP + 16LL*HEADS*LMK*DH)

#define HB  (HEADS*LMK*NP)
#define H_A12F 0LL
#define H_A3   (H_A12F + HB)
#define H_A1T  (H_A3   + HB)
#define H_XNT  (H_A1T  + 2*HB)
#define H_WQ   (H_XNT  + 2*NP*FDIM)
#define H_ZI   (H_WQ   + 2*FDIM*768LL)
#define H_OCT  (H_ZI   + 2*HEADS*LMK*LMK)
#define H_WO   (H_OCT  + 2*NP*FDIM)
#define H_END  (H_WO   + 2*FDIM*FDIM)
#define TOTALF (OFF_H16 + (H_END + 1)/2)

__device__ __align__(128) float g_buf[TOTALF];
__device__ int g_rowmax;

// ---------- LayerNorm + front pad (also zeroes g_rowmax) ----------
__global__ void __launch_bounds__(256) ln_kernel(const float* __restrict__ x,
                                                 const float* __restrict__ g,
                                                 const float* __restrict__ b,
                                                 int pad)
{
    if (blockIdx.x == 0 && threadIdx.x == 0) g_rowmax = 0;
    int r = blockIdx.x, c = threadIdx.x;
    float* xn = g_buf + OFF_XN;
    if (r < pad) { xn[(long long)r*FDIM + c] = 0.f; return; }
    float v = x[(long long)(r - pad)*FDIM + c];
    float s = v, s2 = v*v;
    #pragma unroll
    for (int o = 16; o; o >>= 1) {
        s  += __shfl_xor_sync(0xffffffffu, s,  o);
        s2 += __shfl_xor_sync(0xffffffffu, s2, o);
    }
    __shared__ float ss[8], ss2[8];
    int w = c >> 5;
    if ((c & 31) == 0) { ss[w] = s; ss2[w] = s2; }
    __syncthreads();
    s = 0.f; s2 = 0.f;
    #pragma unroll
    for (int i = 0; i < 8; i++) { s += ss[i]; s2 += ss2[i]; }
    float mean = s * (1.f/256.f);
    float var  = s2 * (1.f/256.f) - mean*mean;
    xn[(long long)r*FDIM + c] = (v - mean) * rsqrtf(var + 1e-5f) * g[c] + b[c];
}

// ---------- fp32 tile GEMM (small K=32 score GEMMs) ----------
__global__ void __launch_bounds__(256, 2) bgemm128(
    float* __restrict__ C, const float* __restrict__ A, const float* __restrict__ B,
    int Ni, int Ki, long long sA, long long sB, long long sC)
{
    A += (long long)blockIdx.z * sA;
    B += (long long)blockIdx.z * sB;
    C += (long long)blockIdx.z * sC;
    const int m0 = blockIdx.y * 128, n0 = blockIdx.x * 128;
    __shared__ float As[8][128];
    __shared__ float Bs[8][128];
    const int tid = threadIdx.x;
    const int tx = tid & 15, ty = tid >> 4;
    float acc[8][8];
    #pragma unroll
    for (int i = 0; i < 8; i++)
        #pragma unroll
        for (int j = 0; j < 8; j++) acc[i][j] = 0.f;
    const int am = tid >> 1, ak = (tid & 1) << 2;
    const int bk = tid >> 5, bn = (tid & 31) << 2;
    for (int k0 = 0; k0 < Ki; k0 += 8) {
        float4 a4 = *(const float4*)(A + (long long)(m0 + am)*Ki + (k0 + ak));
        float4 b4 = *(const float4*)(B + (long long)(k0 + bk)*Ni + (n0 + bn));
        As[ak+0][am] = a4.x; As[ak+1][am] = a4.y; As[ak+2][am] = a4.z; As[ak+3][am] = a4.w;
        *(float4*)&Bs[bk][bn] = b4;
        __syncthreads();
        #pragma unroll
        for (int kk = 0; kk < 8; kk++) {
            float a[8], b[8];
            *(float4*)(a)     = *(const float4*)&As[kk][ty*4];
            *(float4*)(a + 4) = *(const float4*)&As[kk][64 + ty*4];
            *(float4*)(b)     = *(const float4*)&Bs[kk][tx*4];
            *(float4*)(b + 4) = *(const float4*)&Bs[kk][64 + tx*4];
            #pragma unroll
            for (int i = 0; i < 8; i++)
                #pragma unroll
                for (int j = 0; j < 8; j++)
                    acc[i][j] += a[i]*b[j];
        }
        __syncthreads();
    }
    #pragma unroll
    for (int i = 0; i < 8; i++) {
        int m = m0 + ((i >> 2) << 6) + ty*4 + (i & 3);
        #pragma unroll
        for (int jh = 0; jh < 2; jh++) {
            float4 r;
            r.x = acc[i][jh*4+0]; r.y = acc[i][jh*4+1];
            r.z = acc[i][jh*4+2]; r.w = acc[i][jh*4+3];
            *(float4*)(C + (long long)m*Ni + n0 + jh*64 + tx*4) = r;
        }
    }
}

// ---------- fused Newton-Schulz pinv (4-CTA cluster per head) ----------
__device__ __forceinline__ void csync() {
    asm volatile("barrier.cluster.arrive.aligned;" ::: "memory");
    asm volatile("barrier.cluster.wait.aligned;" ::: "memory");
}

__device__ __forceinline__ void gemm64_dev(
    float* __restrict__ C, const float* __restrict__ A, const float* __restrict__ B,
    int m0, int n0, float ids, float es, float alpha,
    float (*As)[64], float (*Bs)[64])
{
    int tid = threadIdx.x;
    int tx = tid & 15, ty = tid >> 4;
    float acc[4][4];
    #pragma unroll
    for (int i = 0; i < 4; i++)
        #pragma unroll
        for (int j = 0; j < 4; j++) acc[i][j] = 0.f;
    int am = tid >> 2, ak = (tid & 3) << 2;
    int bk = tid >> 4, bn = (tid & 15) << 2;
    for (int k0 = 0; k0 < 128; k0 += 16) {
        float4 a4 = *(const float4*)(A + (m0 + am)*128 + k0 + ak);
        float4 b4 = *(const float4*)(B + (k0 + bk)*128 + n0 + bn);
        b4.x *= es; b4.y *= es; b4.z *= es; b4.w *= es;
        int kg = k0 + bk, ng = n0 + bn;
        if      (kg == ng)     b4.x += ids;
        else if (kg == ng + 1) b4.y += ids;
        else if (kg == ng + 2) b4.z += ids;
        else if (kg == ng + 3) b4.w += ids;
        As[ak+0][am] = a4.x; As[ak+1][am] = a4.y; As[ak+2][am] = a4.z; As[ak+3][am] = a4.w;
        *(float4*)&Bs[bk][bn] = b4;
        __syncthreads();
        #pragma unroll
        for (int kk = 0; kk < 16; kk++) {
            float a[4], b[4];
            *(float4*)a = *(const float4*)&As[kk][ty*4];
            *(float4*)b = *(const float4*)&Bs[kk][tx*4];
            #pragma unroll
            for (int i = 0; i < 4; i++)
                #pragma unroll
                for (int j = 0; j < 4; j++) acc[i][j] += a[i]*b[j];
        }
        __syncthreads();
    }
    #pragma unroll
    for (int i = 0; i < 4; i++) {
        float4 r;
        r.x = alpha*acc[i][0]; r.y = alpha*acc[i][1];
        r.z = alpha*acc[i][2]; r.w = alpha*acc[i][3];
        *(float4*)(C + (m0 + ty*4 + i)*128 + n0 + tx*4) = r;
    }
}

__global__ void __cluster_dims__(4,1,1) __launch_bounds__(256) pinv_fused()
{
    __shared__ float As[16][64];
    __shared__ float Bs[16][64];
    int q = blockIdx.x, h = blockIdx.y;
    int m0 = (q >> 1) * 64, n0 = (q & 1) * 64;
    long long s2 = (long long)LMK*LMK;
    float* A2 = g_buf + OFF_A2 + h*s2;
    float* Z  = g_buf + OFF_Z  + h*s2;
    float* Z2 = g_buf + OFF_Z2 + h*s2;
    float* AZ = g_buf + OFF_AZ + h*s2;
    float* T1 = g_buf + OFF_T1 + h*s2;
    float* T2 = g_buf + OFF_T2 + h*s2;
    float* zi = Z; float* zo = Z2;
    #pragma unroll 1
    for (int it = 0; it < 6; it++) {
        gemm64_dev(AZ, A2, zi, m0, n0, 0.f,   1.f, 1.f,   As, Bs); csync();
        gemm64_dev(T1, AZ, AZ, m0, n0, 7.f,  -1.f, 1.f,   As, Bs); csync();
        gemm64_dev(T2, AZ, T1, m0, n0, 15.f, -1.f, 1.f,   As, Bs); csync();
        gemm64_dev(zo, zi, T2, m0, n0, 13.f, -1.f, 0.25f, As, Bs); csync();
        float* t = zi; zi = zo; zo = t;
    }
}

// ---------- landmark means (8 warps / block) ----------
__global__ void __launch_bounds__(256) landmarks(int N)
{
    int h = blockIdx.y;
    int w = threadIdx.x >> 5, lane = threadIdx.x & 31;
    int i = blockIdx.x * 8 + w;
    int l = N / LMK;
    const float* q = g_buf + OFF_Q + ((long long)h*N + (long long)i*l)*DH;
    const float* k = g_buf + OFF_K + ((long long)h*N + (long long)i*l)*DH;
    float sq = 0.f, sk = 0.f;
    for (int r = 0; r < l; r++) { sq += q[r*DH + lane]; sk += k[r*DH + lane]; }
    float inv = 1.f / (float)l;
    g_buf[OFF_QL  + ((long long)h*LMK + i)*DH + lane] = sq * inv;
    g_buf[OFF_KLT + ((long long)h*DH + lane)*LMK + i] = sk * inv;
}

// ---------- generic row softmax (L<=256) ----------
template <int CNT>
__global__ void softmax_rows(float* __restrict__ p, int L)
{
    long long row = blockIdx.x;
    float* r = p + row * (long long)L;
    float v[CNT];
    float mx = -1e30f;
    #pragma unroll
    for (int t = 0; t < CNT; t++) {
        int i = threadIdx.x + t*256;
        v[t] = (i < L) ? r[i] : -1e30f;
        mx = fmaxf(mx, v[t]);
    }
    #pragma unroll
    for (int o = 16; o; o >>= 1) mx = fmaxf(mx, __shfl_xor_sync(0xffffffffu, mx, o));
    __shared__ float sh[8], sh2[8];
    int w = threadIdx.x >> 5;
    if ((threadIdx.x & 31) == 0) sh[w] = mx;
    __syncthreads();
    mx = sh[0];
    #pragma unroll
    for (int i = 1; i < 8; i++) mx = fmaxf(mx, sh[i]);
    float sum = 0.f;
    #pragma unroll
    for (int t = 0; t < CNT; t++) {
        int i = threadIdx.x + t*256;
        if (i < L) { v[t] = __expf(v[t] - mx); sum += v[t]; }
    }
    #pragma unroll
    for (int o = 16; o; o >>= 1) sum += __shfl_xor_sync(0xffffffffu, sum, o);
    if ((threadIdx.x & 31) == 0) sh2[w] = sum;
    __syncthreads();
    sum = 0.f;
    #pragma unroll
    for (int i = 0; i < 8; i++) sum += sh2[i];
    float inv = 1.f / sum;
    #pragma unroll
    for (int t = 0; t < CNT; t++) {
        int i = threadIdx.x + t*256;
        if (i < L) r[i] = v[t] * inv;
    }
}

// ---------- fused softmax(A1) + transpose + fp16 hi/lo split ----------
__global__ void __launch_bounds__(256) softmax_a1_split(
        const float* __restrict__ A1, __half* __restrict__ hi,
        __half* __restrict__ lo, int N)
{
    __shared__ float sm[32][132];
    int h = blockIdx.y, t0 = blockIdx.x * 32;
    const float* base = A1 + ((long long)h*N + t0)*LMK;
    for (int i = threadIdx.x; i < 32*32; i += 256) {
        int r = i >> 5, c4 = (i & 31) << 2;
        *(float4*)&sm[r][c4] = *(const float4*)(base + r*LMK + c4);
    }
    __syncthreads();
    int w = threadIdx.x >> 5, lane = threadIdx.x & 31;
    #pragma unroll
    for (int j = 0; j < 4; j++) {
        int r = w*4 + j;
        float v0 = sm[r][lane], v1 = sm[r][lane+32], v2 = sm[r][lane+64], v3 = sm[r][lane+96];
        float mx = fmaxf(fmaxf(v0, v1), fmaxf(v2, v3));
        #pragma unroll
        for (int o = 16; o; o >>= 1) mx = fmaxf(mx, __shfl_xor_sync(0xffffffffu, mx, o));
        v0 = __expf(v0 - mx); v1 = __expf(v1 - mx); v2 = __expf(v2 - mx); v3 = __expf(v3 - mx);
        float s = v0 + v1 + v2 + v3;
        #pragma unroll
        for (int o = 16; o; o >>= 1) s += __shfl_xor_sync(0xffffffffu, s, o);
        float inv = 1.f / s;
        sm[r][lane] = v0*inv; sm[r][lane+32] = v1*inv;
        sm[r][lane+64] = v2*inv; sm[r][lane+96] = v3*inv;
    }
    __syncthreads();
    #pragma unroll
    for (int j = 0; j < 16; j++) {
        int k = w*16 + j;
        float v = sm[lane][k];
        __half hv = __float2half(v);
        __half lv = __float2half(v - __half2float(hv));
        long long o = ((long long)h*LMK + k)*N + t0 + lane;
        hi[o] = hv; lo[o] = lv;
    }
}

// ---------- A3 softmax (L = N), emits fp16 ONLY ----------
__global__ void __launch_bounds__(256) softmax_a3(const float* __restrict__ p,
                                                  __half* __restrict__ ph, int L)
{
    long long row = blockIdx.x;
    const float* r = p + row * (long long)L;
    __half* rh = ph + row * (long long)L;
    float v[16];
    float mx = -1e30f;
    #pragma unroll
    for (int t = 0; t < 16; t++) {
        int i = threadIdx.x + t*256;
        v[t] = r[i];
        mx = fmaxf(mx, v[t]);
    }
    #pragma unroll
    for (int o = 16; o; o >>= 1) mx = fmaxf(mx, __shfl_xor_sync(0xffffffffu, mx, o));
    __shared__ float sh[8], sh2[8];
    int w = threadIdx.x >> 5;
    if ((threadIdx.x & 31) == 0) sh[w] = mx;
    __syncthreads();
    mx = sh[0];
    #pragma unroll
    for (int i = 1; i < 8; i++) mx = fmaxf(mx, sh[i]);
    float sum = 0.f;
    #pragma unroll
    for (int t = 0; t < 16; t++) { v[t] = __expf(v[t] - mx); sum += v[t]; }
    #pragma unroll
    for (int o = 16; o; o >>= 1) sum += __shfl_xor_sync(0xffffffffu, sum, o);
    if ((threadIdx.x & 31) == 0) sh2[w] = sum;
    __syncthreads();
    sum = 0.f;
    #pragma unroll
    for (int i = 0; i < 8; i++) sum += sh2[i];
    float inv = 1.f / sum;
    #pragma unroll
    for (int t = 0; t < 16; t++) {
        int i = threadIdx.x + t*256;
        rh[i] = __float2half(v[t] * inv);
    }
}

// ---------- pinv norm ----------
__global__ void colmax_a2()
{
    int h = blockIdx.x, j = threadIdx.x;
    const float* a = g_buf + OFF_A2 + (long long)h*LMK*LMK;
    float s = 0.f;
    for (int i = 0; i < LMK; i++) s += a[i*LMK + j];
    #pragma unroll
    for (int o = 16; o; o >>= 1) s = fmaxf(s, __shfl_xor_sync(0xffffffffu, s, o));
    __shared__ float sh[4];
    if ((j & 31) == 0) sh[j >> 5] = s;
    __syncthreads();
    if (j == 0) {
        s = fmaxf(fmaxf(sh[0], sh[1]), fmaxf(sh[2], sh[3]));
        atomicMax(&g_rowmax, __float_as_int(s));
    }
}

__global__ void zinit()
{
    long long idx = (long long)blockIdx.x * 256 + threadIdx.x;
    if (idx >= (long long)HEADS*LMK*LMK) return;
    int h = (int)(idx >> 14), rem = (int)(idx & 16383);
    int i = rem >> 7, j = rem & 127;
    float row = __int_as_float(g_rowmax);
    g_buf[OFF_Z + idx] = g_buf[OFF_A2 + ((long long)h*LMK + j)*LMK + i] / row;
}

// ---------- av = attn3(fp16) @ v, split-K ----------
#define AVKC 16
__global__ void __launch_bounds__(256) av_part(const __half* __restrict__ A3h, int N)
{
    int kc = blockIdx.x, h = blockIdx.y;
    const int KLEN = N / AVKC;
    __shared__ float vs[256*32];
    const float* vh = g_buf + OFF_V + ((long long)h*N + (long long)kc*KLEN)*DH;
    for (int i = threadIdx.x; i < KLEN*DH/4; i += 256)
        ((float4*)vs)[i] = ((const float4*)vh)[i];
    __syncthreads();
    int warp = threadIdx.x >> 5, lane = threadIdx.x & 31;
    for (int r = warp; r < LMK; r += 8) {
        const __half* arow = A3h + ((long long)h*LMK + r)*N + kc*KLEN;
        float acc = 0.f;
        #pragma unroll 2
        for (int k = 0; k < KLEN; k += 8) {
            __half2 a01 = *(const __half2*)(arow + k);
            __half2 a23 = *(const __half2*)(arow + k + 2);
            __half2 a45 = *(const __half2*)(arow + k + 4);
            __half2 a67 = *(const __half2*)(arow + k + 6);
            float2 f01 = __half22float2(a01), f23 = __half22float2(a23);
            float2 f45 = __half22float2(a45), f67 = __half22float2(a67);
            acc += f01.x * vs[(k+0)*DH + lane] + f01.y * vs[(k+1)*DH + lane];
            acc += f23.x * vs[(k+2)*DH + lane] + f23.y * vs[(k+3)*DH + lane];
            acc += f45.x * vs[(k+4)*DH + lane] + f45.y * vs[(k+5)*DH + lane];
            acc += f67.x * vs[(k+6)*DH + lane] + f67.y * vs[(k+7)*DH + lane];
        }
        g_buf[OFF_AVP + ((long long)kc*HEADS*LMK + (long long)h*LMK + r)*DH + lane] = acc;
    }
}
__global__ void av_reduce()
{
    int idx = blockIdx.x*256 + threadIdx.x;
    if (idx >= HEADS*LMK*DH) return;
    float s = 0.f;
    #pragma unroll
    for (int kc = 0; kc < AVKC; kc++)
        s += g_buf[OFF_AVP + (long long)kc*HEADS*LMK*DH + idx];
    g_buf[OFF_AV + idx] = s;
}

// ---------- ocat = concat_h( a12(fp16) @ av + depthwise_conv(v) ) ----------
__global__ void __launch_bounds__(128) ocat_kernel(const float* __restrict__ rk,
                                                   const __half* __restrict__ A12f, int N)
{
    int h = blockIdx.y, tid = threadIdx.x;
    int t = blockIdx.x * 128 + tid;
    __shared__ float avs[LMK][32];
    __shared__ float kr[33];
    const float* av = g_buf + OFF_AV + (long long)h*LMK*DH;
    #pragma unroll
    for (int c4 = 0; c4 < 8; c4++)
        *(float4*)&avs[tid][c4*4] = *(const float4*)(av + tid*DH + c4*4);
    if (tid < 33) kr[tid] = rk[h*33 + tid];
    __syncthreads();
    const __half* a12row = A12f + ((long long)h*N + t)*LMK;
    float acc[32];
    #pragma unroll
    for (int c = 0; c < 32; c++) acc[c] = 0.f;
    for (int k = 0; k < LMK; k += 2) {
        __half2 a2 = *(const __half2*)(a12row + k);
        float2 af = __half22float2(a2);
        #pragma unroll
        for (int c = 0; c < 32; c++) acc[c] += af.x * avs[k][c] + af.y * avs[k+1][c];
    }
    const float* vh = g_buf + OFF_V + (long long)h*N*DH;
    for (int j = 0; j < 33; j++) {
        int tt = t + j - 16;
        if (tt >= 0 && tt < N) {
            float w = kr[j];
            const float4* vr = (const float4*)(vh + (long long)tt*DH);
            #pragma unroll
            for (int c4 = 0; c4 < 8; c4++) {
                float4 vv = vr[c4];
                acc[c4*4+0] += w*vv.x; acc[c4*4+1] += w*vv.y;
                acc[c4*4+2] += w*vv.z; acc[c4*4+3] += w*vv.w;
            }
        }
    }
    float* o = g_buf + OFF_OCAT + (long long)t*FDIM + h*DH;
    #pragma unroll
    for (int c4 = 0; c4 < 8; c4++)
        *(float4*)(o + c4*4) = make_float4(acc[c4*4], acc[c4*4+1], acc[c4*4+2], acc[c4*4+3]);
}

// ---------- final residual epilogue ----------
__global__ void epilogue(const float* __restrict__ x, const float* __restrict__ b_out,
                         float* __restrict__ out, int pad)
{
    int t = blockIdx.x, c = threadIdx.x;
    long long i = (long long)t*FDIM + c;
    out[i] = x[i] + g_buf[OFF_PROJ + (long long)(t + pad)*FDIM + c] + b_out[c];
}

__global__ void tail_k(float* p, float a, float b) { p[0] = a; p[1] = b; }

// ============= fp16 prep kernels =============
__global__ void __launch_bounds__(256) split_h(const float* __restrict__ src,
                                               __half* __restrict__ hi,
                                               __half* __restrict__ lo,
                                               long long total4)
{
    long long i = (long long)blockIdx.x*256 + threadIdx.x;
    if (i >= total4) return;
    float4 v = ((const float4*)src)[i];
    __half h0 = __float2half(v.x), h1 = __float2half(v.y);
    __half h2 = __float2half(v.z), h3 = __float2half(v.w);
    __half l0 = __float2half(v.x - __half2float(h0));
    __half l1 = __float2half(v.y - __half2float(h1));
    __half l2 = __float2half(v.z - __half2float(h2));
    __half l3 = __float2half(v.w - __half2float(h3));
    ((ushort4*)hi)[i] = make_ushort4(__half_as_ushort(h0), __half_as_ushort(h1),
                                     __half_as_ushort(h2), __half_as_ushort(h3));
    ((ushort4*)lo)[i] = make_ushort4(__half_as_ushort(l0), __half_as_ushort(l1),
                                     __half_as_ushort(l2), __half_as_ushort(l3));
}

__global__ void __launch_bounds__(256) splitT_h(const float* __restrict__ src,
                                                __half* __restrict__ hi,
                                                __half* __restrict__ lo,
                                                int M, int K)
{
    __shared__ float t[32][33];
    long long bs = (long long)blockIdx.z * M * K;
    int m0 = blockIdx.x * 32, k0 = blockIdx.y * 32;
    int tx = threadIdx.x & 31, ty = threadIdx.x >> 5;
    #pragma unroll
    for (int j = 0; j < 4; j++) {
        int ml = ty + 8*j;
        t[ml][tx] = src[bs + (long long)(m0 + ml)*K + k0 + tx];
    }
    __syncthreads();
    #pragma unroll
    for (int j = 0; j < 4; j++) {
        int kl = ty + 8*j;
        float v = t[tx][kl];
        __half hv = __float2half(v);
        __half lv = __float2half(v - __half2float(hv));
        long long o = bs + (long long)(k0 + kl)*M + m0 + tx;
        hi[o] = hv; lo[o] = lv;
    }
}

// ============= mma helpers =============
__device__ __forceinline__ void ldsm4(uint32_t* r, uint32_t addr) {
    asm volatile("ldmatrix.sync.aligned.m8n8.x4.shared.b16 {%0,%1,%2,%3}, [%4];"
        : "=r"(r[0]), "=r"(r[1]), "=r"(r[2]), "=r"(r[3]) : "r"(addr));
}
__device__ __forceinline__ void ldsm4t(uint32_t* r, uint32_t addr) {
    asm volatile("ldmatrix.sync.aligned.m8n8.x4.trans.shared.b16 {%0,%1,%2,%3}, [%4];"
        : "=r"(r[0]), "=r"(r[1]), "=r"(r[2]), "=r"(r[3]) : "r"(addr));
}
__device__ __forceinline__ void mma16816(float* c, const uint32_t* a, const uint32_t* b) {
    asm volatile("mma.sync.aligned.m16n8k16.row.col.f32.f16.f16.f32 "
        "{%0,%1,%2,%3}, {%4,%5,%6,%7}, {%8,%9}, {%0,%1,%2,%3};"
        : "+f"(c[0]), "+f"(c[1]), "+f"(c[2]), "+f"(c[3])
        : "r"(a[0]), "r"(a[1]), "r"(a[2]), "r"(a[3]), "r"(b[0]), "r"(b[1]));
}
__device__ __forceinline__ void cpasync16(uint32_t saddr, const void* gaddr) {
    asm volatile("cp.async.cg.shared.global [%0], [%1], 16;\n" :: "r"(saddr), "l"(gaddr));
}
__device__ __forceinline__ void cpcommit() { asm volatile("cp.async.commit_group;\n"); }
template <int NN>
__device__ __forceinline__ void cpwait() { asm volatile("cp.async.wait_group %0;\n" :: "n"(NN)); }
__device__ __forceinline__ void stcs2(float* p, float x, float y) {
    asm volatile("st.global.cs.v2.f32 [%0], {%1,%2};" :: "l"(p), "f"(x), "f"(y) : "memory");
}

// ============= pipelined fp16 3-prod GEMM, templated epilogue =============
// EPI 0: write fp32 C (+ optional fp16 Ch)
// EPI 1: qkv scatter: write Q(scaled)/K/KT/V directly (ldA = token count)
// EPI 2: write ONLY fp16 Ch
template <int EPI>
__global__ void __launch_bounds__(256, 2) hgemm3(float* __restrict__ C,
        const __half* __restrict__ Ah, const __half* __restrict__ Al,
        const __half* __restrict__ Bh, const __half* __restrict__ Bl,
        int ldA, int N, int K, long long sA, long long sB, long long sC,
        __half* __restrict__ Ch)
{
    constexpr int D = 3;
    Ah += (long long)blockIdx.z * sA;  Al += (long long)blockIdx.z * sA;
    Bh += (long long)blockIdx.z * sB;  Bl += (long long)blockIdx.z * sB;
    if (EPI == 0) C  += (long long)blockIdx.z * sC;
    if (Ch) Ch += (long long)blockIdx.z * sC;
    const int m0 = blockIdx.y * 128, n0 = blockIdx.x * 128;

    extern __shared__ __align__(16) uint8_t dsm[];
    const uint32_t sb = (uint32_t)__cvta_generic_to_shared(dsm);
    const int tid = threadIdx.x, lane = tid & 31, warp = tid >> 5;
    const int wm = warp >> 1, wn = warp & 1;

    const int T = K >> 5;
    int li0 = tid, li1 = tid + 256;
    int lk0 = li0 >> 4, ls0 = li0 & 15;
    int lk1 = li1 >> 4, ls1 = li1 & 15;
    uint32_t d0 = (uint32_t)(lk0*256 + ((ls0 ^ (lk0 & 7)) << 4));
    uint32_t d1 = (uint32_t)(lk1*256 + ((ls1 ^ (lk1 & 7)) << 4));

    auto load_stage = [&](int stage, int chunk) {
        int kb = chunk << 5;
        uint32_t s0 = sb + (uint32_t)(stage*4) * 8192u;
        long long ga0 = (long long)(kb + lk0)*ldA + m0 + ls0*8;
        long long ga1 = (long long)(kb + lk1)*ldA + m0 + ls1*8;
        long long gb0 = (long long)(kb + lk0)*N   + n0 + ls0*8;
        long long gb1 = (long long)(kb + lk1)*N   + n0 + ls1*8;
        cpasync16(s0 +         d0, Ah + ga0);  cpasync16(s0 +         d1, Ah + ga1);
        cpasync16(s0 +  8192 + d0, Al + ga0);  cpasync16(s0 +  8192 + d1, Al + ga1);
        cpasync16(s0 + 16384 + d0, Bh + gb0);  cpasync16(s0 + 16384 + d1, Bh + gb1);
        cpasync16(s0 + 24576 + d0, Bl + gb0);  cpasync16(s0 + 24576 + d1, Bl + gb1);
    };

    float acc[2][8][4];
    #pragma unroll
    for (int i = 0; i < 2; i++)
        #pragma unroll
        for (int j = 0; j < 8; j++)
            #pragma unroll
            for (int q = 0; q < 4; q++) acc[i][j][q] = 0.f;

    #pragma unroll
    for (int s = 0; s < D-1; s++) {
        if (s < T) load_stage(s, s);
        cpcommit();
    }

    for (int it = 0; it < T; it++) {
        cpwait<D-2>();
        __syncthreads();
        int st = it % D;
        uint32_t sA0 = sb + (uint32_t)(st*4) * 8192u;

        #pragma unroll
        for (int ks = 0; ks < 32; ks += 16) {
            uint32_t ah[2][4], al[2][4];
            #pragma unroll
            for (int mt = 0; mt < 2; mt++) {
                int kr  = ks + (lane & 7) + ((lane >> 4) << 3);
                int seg = (wm*4 + mt*2) + ((lane >> 3) & 1);
                uint32_t a = (uint32_t)(kr*256 + ((seg ^ (kr & 7)) << 4));
                ldsm4t(ah[mt], sA0 + a);
                ldsm4t(al[mt], sA0 + 8192 + a);
            }
            #pragma unroll
            for (int np = 0; np < 4; np++) {
                int kr  = ks + (lane & 7) + (((lane >> 3) & 1) << 3);
                int seg = (wn*8 + np*2) + ((lane >> 4) & 1);
                uint32_t a = (uint32_t)(kr*256 + ((seg ^ (kr & 7)) << 4));
                uint32_t bh[4], bl[4];
                ldsm4t(bh, sA0 + 16384 + a);
                ldsm4t(bl, sA0 + 24576 + a);
                #pragma unroll
                for (int mt = 0; mt < 2; mt++) {
                    mma16816(acc[mt][np*2+0], ah[mt], bh + 0);
                    mma16816(acc[mt][np*2+0], al[mt], bh + 0);
                    mma16816(acc[mt][np*2+0], ah[mt], bl + 0);
                    mma16816(acc[mt][np*2+1], ah[mt], bh + 2);
                    mma16816(acc[mt][np*2+1], al[mt], bh + 2);
                    mma16816(acc[mt][np*2+1], ah[mt], bl + 2);
                }
            }
        }
        int nx = it + D - 1;
        if (nx < T) load_stage(nx % D, nx);
        cpcommit();
    }

    const int g = lane >> 2, t4 = lane & 3;
    #pragma unroll
    for (int mt = 0; mt < 2; mt++) {
        int mb = m0 + wm*32 + mt*16 + g;
        #pragma unroll
        for (int nt = 0; nt < 8; nt++) {
            int n = n0 + wn*64 + nt*8 + t4*2;
            #pragma unroll
            for (int half = 0; half < 2; half++) {
                int m = mb + half*8;
                float vx = acc[mt][nt][half*2+0], vy = acc[mt][nt][half*2+1];
                if (EPI == 1) {
                    int which = n >> 8, inner = n & 255;
                    int hh = inner >> 5, dd = inner & 31;
                    long long o = ((long long)hh*ldA + m)*DH + dd;
                    if (which == 0) {
                        g_buf[OFF_Q + o]   = vx * 0.17677669529663688f;
                        g_buf[OFF_Q + o+1] = vy * 0.17677669529663688f;
                    } else if (which == 1) {
                        g_buf[OFF_K + o]   = vx;
                        g_buf[OFF_K + o+1] = vy;
                        g_buf[OFF_KT + ((long long)hh*DH + dd)*ldA + m]     = vx;
                        g_buf[OFF_KT + ((long long)hh*DH + dd + 1)*ldA + m] = vy;
                    } else {
                        g_buf[OFF_V + o]   = vx;
                        g_buf[OFF_V + o+1] = vy;
                    }
                } else {
                    if (EPI == 0)
                        *(float2*)(C + (long long)m*N + n) = make_float2(vx, vy);
                    if (Ch)
                        *(__half2*)(Ch + (long long)m*N + n) = __floats2half2_rn(vx, vy);
                }
            }
        }
    }
}

// ============= att = a12 @ attn3 : A row-major, 2-chunk pipeline =============
__global__ void __launch_bounds__(256, 2) attmma(float* __restrict__ out, int N,
        const __half* __restrict__ A, const __half* __restrict__ B)
{
    const int h = blockIdx.z;
    A += (long long)h * N * LMK;
    B += (long long)h * LMK * N;
    out += (long long)h * N * N;
    const int m0 = blockIdx.y * 128, n0 = blockIdx.x * 128;

    extern __shared__ __align__(16) uint8_t dsm[];
    const uint32_t sb = (uint32_t)__cvta_generic_to_shared(dsm);
    const int tid = threadIdx.x, lane = tid & 31, warp = tid >> 5;
    const int wm = warp >> 1, wn = warp & 1;

    #pragma unroll
    for (int rep = 0; rep < 4; rep++) {
        int i = tid + rep*256;
        int r = i >> 3, s = i & 7;
        uint32_t dA = (uint32_t)(r*256 + ((s ^ (r & 7)) << 4));
        cpasync16(sb + dA, A + (long long)(m0 + r)*LMK + s*8);
    }
    #pragma unroll
    for (int rep = 0; rep < 4; rep++) {
        int i = tid + rep*256;
        int k = i >> 4, s = i & 15;
        uint32_t dB = (uint32_t)(k*256 + ((s ^ (k & 7)) << 4));
        cpasync16(sb + 32768 + dB, B + (long long)k*N + n0 + s*8);
    }
    cpcommit();
    #pragma unroll
    for (int rep = 0; rep < 4; rep++) {
        int i = tid + rep*256;
        int r = i >> 3, s = 8 + (i & 7);
        uint32_t dA = (uint32_t)(r*256 + ((s ^ (r & 7)) << 4));
        cpasync16(sb + dA, A + (long long)(m0 + r)*LMK + s*8);
    }
    #pragma unroll
    for (int rep = 0; rep < 4; rep++) {
        int i = tid + rep*256;
        int k = 64 + (i >> 4), s = i & 15;
        uint32_t dB = (uint32_t)(k*256 + ((s ^ (k & 7)) << 4));
        cpasync16(sb + 32768 + dB, B + (long long)k*N + n0 + s*8);
    }
    cpcommit();

    float acc[2][8][4];
    #pragma unroll
    for (int i = 0; i < 2; i++)
        #pragma unroll
        for (int j = 0; j < 8; j++)
            #pragma unroll
            for (int q = 0; q < 4; q++) acc[i][j][q] = 0.f;

    cpwait<1>();
    __syncthreads();

    #pragma unroll 1
    for (int half = 0; half < 2; half++) {
        if (half == 1) { cpwait<0>(); __syncthreads(); }
        #pragma unroll
        for (int ks = half*64; ks < half*64 + 64; ks += 16) {
            uint32_t ah[2][4];
            #pragma unroll
            for (int mt = 0; mt < 2; mt++) {
                int r   = wm*32 + mt*16 + (lane & 7) + ((lane >> 3) & 1)*8;
                int seg = (ks >> 3) + ((lane >> 4) & 1);
                uint32_t a = (uint32_t)(r*256 + ((seg ^ (r & 7)) << 4));
                ldsm4(ah[mt], sb + a);
            }
            #pragma unroll
            for (int np = 0; np < 4; np++) {
                int kr  = ks + (lane & 7) + (((lane >> 3) & 1) << 3);
                int seg = (wn*8 + np*2) + ((lane >> 4) & 1);
                uint32_t a = (uint32_t)(kr*256 + ((seg ^ (kr & 7)) << 4));
                uint32_t bh[4];
                ldsm4t(bh, sb + 32768 + a);
                #pragma unroll
                for (int mt = 0; mt < 2; mt++) {
                    mma16816(acc[mt][np*2+0], ah[mt], bh + 0);
                    mma16816(acc[mt][np*2+1], ah[mt], bh + 2);
                }
            }
        }
    }

    const int g = lane >> 2, t4 = lane & 3;
    #pragma unroll
    for (int mt = 0; mt < 2; mt++) {
        int m = m0 + wm*32 + mt*16 + g;
        #pragma unroll
        for (int nt = 0; nt < 8; nt++) {
            int n = n0 + wn*64 + nt*8 + t4*2;
            stcs2(out + (long long)m*N + n,     acc[mt][nt][0], acc[mt][nt][1]);
            stcs2(out + (long long)(m+8)*N + n, acc[mt][nt][2], acc[mt][nt][3]);
        }
    }
}

// =======================================================================
extern "C" void kernel_launch(void* const* d_in, const int* in_sizes, int n_in,
                              void* d_out, int out_size)
{
    const float* x     = (const float*)d_in[0];
    const float* ln_g  = (const float*)d_in[1];
    const float* ln_b  = (const float*)d_in[2];
    const float* w_qkv = (const float*)d_in[3];
    const float* w_out = (const float*)d_in[4];
    const float* b_out = (const float*)d_in[5];
    const float* rk    = (const float*)d_in[6];
    float* out = (float*)d_out;

    int n   = in_sizes[0] / FDIM;
    int pad = (LMK - n % LMK) % LMK;
    int N   = n + pad;
    int NB  = N / 128;

    const int SMEM3 = 3*4*8192;   // 96KB
    const int SMEMA = 2*32768;    // 64KB
    cudaFuncSetAttribute(hgemm3<0>, cudaFuncAttributeMaxDynamicSharedMemorySize, SMEM3);
    cudaFuncSetAttribute(hgemm3<1>, cudaFuncAttributeMaxDynamicSharedMemorySize, SMEM3);
    cudaFuncSetAttribute(hgemm3<2>, cudaFuncAttributeMaxDynamicSharedMemorySize, SMEM3);
    cudaFuncSetAttribute(attmma, cudaFuncAttributeMaxDynamicSharedMemorySize, SMEMA);

    float* gb = nullptr;
    cudaGetSymbolAddress((void**)&gb, g_buf);
    float* XN  = gb + OFF_XN;
    float* Q   = gb + OFF_Q;    float* KT  = gb + OFF_KT;
    float* QL  = gb + OFF_QL;   float* KLT = gb + OFF_KLT;
    float* A1  = gb + OFF_A1;   float* A2  = gb + OFF_A2;
    float* A3  = gb + OFF_A3;   float* Z   = gb + OFF_Z;
    float* OC  = gb + OFF_OCAT; float* PRJ = gb + OFF_PROJ;
    __half* H0 = (__half*)(gb + OFF_H16);
    __half *A12f  = H0+H_A12F;
    __half *A3s   = H0+H_A3;
    __half *A1Th  = H0+H_A1T,  *A1Tl = A1Th + HB;
    __half *XNTh  = H0+H_XNT,  *XNTl = XNTh + NP*FDIM;
    __half *WQh   = H0+H_WQ,   *WQl  = WQh + FDIM*768LL;
    __half *ZIh   = H0+H_ZI,   *ZIl  = ZIh + HEADS*LMK*LMK;
    __half *OCTh  = H0+H_OCT,  *OCTl = OCTh + NP*FDIM;
    __half *WOh   = H0+H_WO,   *WOl  = WOh + FDIM*FDIM;

    long long s2 = (long long)LMK*LMK;

    cudaStream_t s1, s2s;
    cudaStreamCreateWithFlags(&s1,  cudaStreamNonBlocking);
    cudaStreamCreateWithFlags(&s2s, cudaStreamNonBlocking);
    cudaEvent_t evRoot, evWQ, evLMK, evA1S, evZI, evAV, evA12, evA3S, evEPI;
    cudaEventCreateWithFlags(&evRoot, cudaEventDisableTiming);
    cudaEventCreateWithFlags(&evWQ,   cudaEventDisableTiming);
    cudaEventCreateWithFlags(&evLMK,  cudaEventDisableTiming);
    cudaEventCreateWithFlags(&evA1S,  cudaEventDisableTiming);
    cudaEventCreateWithFlags(&evZI,   cudaEventDisableTiming);
    cudaEventCreateWithFlags(&evAV,   cudaEventDisableTiming);
    cudaEventCreateWithFlags(&evA12,  cudaEventDisableTiming);
    cudaEventCreateWithFlags(&evA3S,  cudaEventDisableTiming);
    cudaEventCreateWithFlags(&evEPI,  cudaEventDisableTiming);

    cudaEventRecord(evRoot, 0);
    cudaStreamWaitEvent(s1,  evRoot, 0);
    cudaStreamWaitEvent(s2s, evRoot, 0);

    // s1: weight splits
    split_h<<<(int)((FDIM*768LL/4 + 255)/256), 256, 0, s1>>>(w_qkv, WQh, WQl, FDIM*768LL/4);
    cudaEventRecord(evWQ, s1);
    split_h<<<(int)((FDIM*FDIM/4LL + 255)/256), 256, 0, s1>>>(w_out, WOh, WOl, FDIM*FDIM/4LL);

    // 0: LN -> split -> qkv GEMM (fused scatter) -> landmarks
    ln_kernel<<<N, 256>>>(x, ln_g, ln_b, pad);
    splitT_h<<<dim3(N/32, FDIM/32, 1), 256>>>(XN, XNTh, XNTl, N, FDIM);
    cudaStreamWaitEvent(0, evWQ, 0);
    hgemm3<1><<<dim3(6, NB, 1), 256, SMEM3>>>(nullptr, XNTh, XNTl, WQh, WQl, N, 768, 256, 0, 0, 0, nullptr);
    landmarks<<<dim3(LMK/8, HEADS), 256>>>(N);
    cudaEventRecord(evLMK, 0);

    // s2s: A1 scores -> softmax+split
    cudaStreamWaitEvent(s2s, evLMK, 0);
    bgemm128<<<dim3(1, NB, HEADS), 256, 0, s2s>>>(A1, Q, KLT, 128, 32, (long long)N*DH, DH*LMK, (long long)N*LMK);
    softmax_a1_split<<<dim3(N/32, HEADS), 256, 0, s2s>>>(A1, A1Th, A1Tl, N);
    cudaEventRecord(evA1S, s2s);

    // s1: A2 scores -> pinv branch
    cudaStreamWaitEvent(s1, evLMK, 0);
    bgemm128<<<dim3(1, 1, HEADS), 256, 0, s1>>>(A2, QL, KLT, 128, 32, LMK*DH, DH*LMK, s2);
    softmax_rows<1><<<HEADS*LMK, 256, 0, s1>>>(A2, 128);
    colmax_a2<<<HEADS, 128, 0, s1>>>();
    zinit<<<(HEADS*LMK*LMK + 255)/256, 256, 0, s1>>>();
    pinv_fused<<<dim3(4, HEADS), 256, 0, s1>>>();
    split_h<<<(int)((HEADS*s2/4 + 255)/256), 256, 0, s1>>>(Z, ZIh, ZIl, HEADS*s2/4);
    cudaEventRecord(evZI, s1);

    // 0: A3 scores -> softmax (fp16)
    bgemm128<<<dim3(NB, 1, HEADS), 256>>>(A3, QL, KT, N, 32, LMK*DH, (long long)DH*N, (long long)LMK*N);
    softmax_a3<<<HEADS*LMK, 256>>>(A3, A3s, N);
    cudaEventRecord(evA3S, 0);

    // s2s: av branch (after its own A1 work + A3 softmax)
    cudaStreamWaitEvent(s2s, evA3S, 0);
    av_part<<<dim3(AVKC, HEADS), 256, 0, s2s>>>(A3s, N);
    av_reduce<<<(HEADS*LMK*DH + 255)/256, 256, 0, s2s>>>();
    cudaEventRecord(evAV, s2s);

    // 0: a12 GEMM (fp16-only out)
    cudaStreamWaitEvent(0, evA1S, 0);
    cudaStreamWaitEvent(0, evZI, 0);
    hgemm3<2><<<dim3(1, NB, HEADS), 256, SMEM3>>>(nullptr, A1Th, A1Tl, ZIh, ZIl, N, 128, 128,
        (long long)LMK*N, s2, (long long)N*LMK, A12f);
    cudaEventRecord(evA12, 0);

    // s1: output path overlaps attmma
    cudaStreamWaitEvent(s1, evA12, 0);
    cudaStreamWaitEvent(s1, evAV, 0);
    ocat_kernel<<<dim3(NB, HEADS), 128, 0, s1>>>(rk, A12f, N);
    splitT_h<<<dim3(N/32, FDIM/32, 1), 256, 0, s1>>>(OC, OCTh, OCTl, N, FDIM);
    hgemm3<0><<<dim3(2, NB, 1), 256, SMEM3, s1>>>(PRJ, OCTh, OCTl, WOh, WOl, N, 256, 256, 0, 0, 0, nullptr);
    epilogue<<<n, 256, 0, s1>>>(x, b_out, out, pad);
    cudaEventRecord(evEPI, s1);

    // 0: the big att GEMM
    long long base = (long long)n * FDIM;
    attmma<<<dim3(NB, NB, HEADS), 256, SMEMA>>>(out + base, N, A12f, A3s);

    cudaStreamWaitEvent(0, evEPI, 0);
    long long attsz = (long long)HEADS*N*N;
    if ((long long)out_size >= base + attsz + 2)
        tail_k<<<1, 1>>>(out + base + attsz, (float)pad, (float)n);

    cudaStreamCaptureStatus st = cudaStreamCaptureStatusNone;
    cudaStreamIsCapturing(0, &st);
    if (st == cudaStreamCaptureStatusNone) {
        cudaEventDestroy(evRoot); cudaEventDestroy(evWQ); cudaEventDestroy(evLMK);
        cudaEventDestroy(evA1S); cudaEventDestroy(evZI); cudaEventDestroy(evAV);
        cudaEventDestroy(evA12); cudaEventDestroy(evA3S); cudaEventDestroy(evEPI);
        cudaStreamDestroy(s1); cudaStreamDestroy(s2s);
    }
}